// round 8
// baseline (speedup 1.0000x reference)
#include <cuda_runtime.h>
#include <cuda_bf16.h>
#include <math.h>
#include <cstdint>

// ---------------- problem constants ----------------
#define HH      56
#define WW2     56
#define CC      192
#define NHEADS  6
#define WSZ     7
#define SSHIFT  3
#define HIDDIM  768
#define NTOK    49
#define HDIM    32
#define NWINS   4096
#define TTOT    200704
#define SCALEQ  0.17677669529663687f

// ---------------- scratch ----------------
__device__ float  g_X  [(size_t)TTOT * CC];
__device__ float  g_XW [(size_t)TTOT * CC];
__device__ float  g_QKV[(size_t)TTOT * 3 * CC];
__device__ float  g_H1 [(size_t)TTOT * HIDDIM];
__device__ float2 g_ST [TTOT];                    // per-token (mu, rstd)

// split weights, transposed to [N][K] bf16 (hi + lo)
__device__ __nv_bfloat16 g_Wqkv_h[2 * 576 * 192];
__device__ __nv_bfloat16 g_Wqkv_l[2 * 576 * 192];
__device__ __nv_bfloat16 g_Wprj_h[2 * 192 * 192];
__device__ __nv_bfloat16 g_Wprj_l[2 * 192 * 192];
__device__ __nv_bfloat16 g_Wfc1_h[2 * 768 * 192];
__device__ __nv_bfloat16 g_Wfc1_l[2 * 768 * 192];
__device__ __nv_bfloat16 g_Wfc2_h[2 * 192 * 768];
__device__ __nv_bfloat16 g_Wfc2_l[2 * 192 * 768];

// ====================== combined weight transpose + split (one layer) ======================
__global__ __launch_bounds__(256) void wsplit_layer_kernel(
    const float* __restrict__ qkvw, const float* __restrict__ projw,
    const float* __restrict__ fc1w, const float* __restrict__ fc2w,
    __nv_bfloat16* __restrict__ qh, __nv_bfloat16* __restrict__ ql,
    __nv_bfloat16* __restrict__ ph, __nv_bfloat16* __restrict__ pl,
    __nv_bfloat16* __restrict__ f1h, __nv_bfloat16* __restrict__ f1l,
    __nv_bfloat16* __restrict__ f2h, __nv_bfloat16* __restrict__ f2l)
{
    int idx = blockIdx.x * 256 + threadIdx.x;
    const float* W; __nv_bfloat16 *Hp, *Lp; int K, N, off;
    if (idx < 110592)       { W = qkvw; Hp = qh;  Lp = ql;  K = 192; N = 576; off = idx; }
    else if (idx < 147456)  { W = projw; Hp = ph; Lp = pl;  K = 192; N = 192; off = idx - 110592; }
    else if (idx < 294912)  { W = fc1w; Hp = f1h; Lp = f1l; K = 192; N = 768; off = idx - 147456; }
    else if (idx < 442368)  { W = fc2w; Hp = f2h; Lp = f2l; K = 768; N = 192; off = idx - 294912; }
    else return;
    int k = off / N, n = off - k * N;
    float v = W[off];
    __nv_bfloat16 h = __float2bfloat16_rn(v);
    __nv_bfloat16 l = __float2bfloat16_rn(v - __bfloat162float(h));
    Hp[(size_t)n * K + k] = h;
    Lp[(size_t)n * K + k] = l;
}

// ====================== LN stats (per token) ======================
__global__ __launch_bounds__(256) void lnstats_kernel(
    const float* __restrict__ src, float2* __restrict__ st)
{
    int warp = threadIdx.x >> 5, lane = threadIdx.x & 31;
    int m = blockIdx.x * 8 + warp;
    const float* xp = src + (size_t)m * CC;
    float s = 0.f, ss = 0.f;
    #pragma unroll
    for (int j = 0; j < 6; j++) { float v = xp[lane + 32*j]; s += v; ss += v*v; }
    #pragma unroll
    for (int o = 16; o > 0; o >>= 1) {
        s  += __shfl_xor_sync(0xffffffffu, s,  o);
        ss += __shfl_xor_sync(0xffffffffu, ss, o);
    }
    if (lane == 0) {
        float mu = s * (1.f / CC);
        float rstd = rsqrtf(ss * (1.f / CC) - mu * mu + 1e-5f);
        st[m] = make_float2(mu, rstd);
    }
}

// ====================== window attention ======================
__global__ __launch_bounds__(128) void attn_kernel(
    const float* __restrict__ qkv, float* __restrict__ outp,
    const float* __restrict__ rpb, int shifted)
{
    int win = blockIdx.x / NHEADS;
    int hd  = blockIdx.x % NHEADS;
    __shared__ float q[NTOK][HDIM + 1];
    __shared__ float k[NTOK][HDIM + 1];
    __shared__ float v[NTOK][HDIM + 1];
    __shared__ float sc[NTOK][52];
    __shared__ int   lab[NTOK];
    int tid = threadIdx.x;

    const float* base = qkv + (size_t)win * NTOK * 576 + hd * HDIM;
    for (int idx = tid; idx < NTOK * HDIM; idx += 128) {
        int i = idx >> 5, d = idx & 31;
        const float* row = base + (size_t)i * 576 + d;
        q[i][d] = row[0]   * SCALEQ;
        k[i][d] = row[192];
        v[i][d] = row[384];
    }
    if (shifted && tid < NTOK) {
        int wl = win & 63;
        int h = (wl >> 3) * WSZ + tid / WSZ;
        int w = (wl & 7)  * WSZ + tid % WSZ;
        int rc = (h < HH  - WSZ) ? 0 : ((h < HH  - SSHIFT) ? 1 : 2);
        int cc = (w < WW2 - WSZ) ? 0 : ((w < WW2 - SSHIFT) ? 1 : 2);
        lab[tid] = rc * 3 + cc;
    }
    __syncthreads();

    for (int idx = tid; idx < NTOK * NTOK; idx += 128) {
        int i = idx / NTOK, j = idx - i * NTOK;
        float acc = 0.f;
        #pragma unroll
        for (int d = 0; d < HDIM; d++) acc += q[i][d] * k[j][d];
        int ridx = (i / WSZ - j / WSZ + WSZ - 1) * (2 * WSZ - 1)
                 + (i % WSZ - j % WSZ + WSZ - 1);
        acc += rpb[ridx * NHEADS + hd];
        if (shifted && lab[i] != lab[j]) acc -= 100.f;
        sc[i][j] = acc;
    }
    __syncthreads();

    int warp = tid >> 5, lane = tid & 31;
    for (int i = warp; i < NTOK; i += 4) {
        float a0 = (lane < NTOK)      ? sc[i][lane]      : -1e30f;
        float a1 = (lane + 32 < NTOK) ? sc[i][lane + 32] : -1e30f;
        float mx = fmaxf(a0, a1);
        #pragma unroll
        for (int o = 16; o > 0; o >>= 1) mx = fmaxf(mx, __shfl_xor_sync(0xffffffffu, mx, o));
        float e0 = (lane < NTOK)      ? __expf(a0 - mx) : 0.f;
        float e1 = (lane + 32 < NTOK) ? __expf(a1 - mx) : 0.f;
        float sum = e0 + e1;
        #pragma unroll
        for (int o = 16; o > 0; o >>= 1) sum += __shfl_xor_sync(0xffffffffu, sum, o);
        float inv = 1.f / sum;
        if (lane < NTOK)      sc[i][lane]      = e0 * inv;
        if (lane + 32 < NTOK) sc[i][lane + 32] = e1 * inv;
    }
    __syncthreads();

    float* obase = outp + (size_t)win * NTOK * CC + hd * HDIM;
    for (int idx = tid; idx < NTOK * HDIM; idx += 128) {
        int i = idx >> 5, d = idx & 31;
        float acc = 0.f;
        #pragma unroll
        for (int j = 0; j < NTOK; j++) acc += sc[i][j] * v[j][d];
        obase[(size_t)i * CC + d] = acc;
    }
}

// ====================== bf16 hi/lo tensor-core GEMM ======================
// CTA tile 128x192, BK=32. 8 warps in 2x4 grid, warp tile 64x48 (mt=4, nt=6).
// 3 passes: Ah*Bh + Al*Bh + Ah*Bl (fp32-grade accuracy).
// EPI:  0 store; 1 win-reverse(+unshift) residual; 2 exact GELU store; 3 residual
// LNM:  0 raw A; 1 LN token-order; 2 LN + window(+shift) gather
#define BK      32
#define BN      192
#define STRD    40
#define A_SZ    (128 * STRD)                   // 5120 elems
#define B_SZ    (BN * STRD)                    // 7680 elems
#define OFF_AHI 0
#define OFF_ALO A_SZ
#define OFF_BHI (2 * A_SZ)
#define OFF_BLO (2 * A_SZ + B_SZ)
#define STAGE   (2 * A_SZ + 2 * B_SZ)          // 25600 elems = 51200 B
#define GSMEM   (2 * STAGE * 2)                // 102400 B

__device__ __forceinline__ void split8(const float* f, uint4& hi, uint4& lo)
{
    uint32_t hb[8], lb[8];
    #pragma unroll
    for (int i = 0; i < 8; i++) {
        __nv_bfloat16 h = __float2bfloat16_rn(f[i]);
        __nv_bfloat16 l = __float2bfloat16_rn(f[i] - __bfloat162float(h));
        hb[i] = (uint32_t)__bfloat16_as_ushort(h);
        lb[i] = (uint32_t)__bfloat16_as_ushort(l);
    }
    hi.x = hb[0] | (hb[1] << 16); hi.y = hb[2] | (hb[3] << 16);
    hi.z = hb[4] | (hb[5] << 16); hi.w = hb[6] | (hb[7] << 16);
    lo.x = lb[0] | (lb[1] << 16); lo.y = lb[2] | (lb[3] << 16);
    lo.z = lb[4] | (lb[5] << 16); lo.w = lb[6] | (lb[7] << 16);
}

__device__ __forceinline__ void mma16816(float* c, const uint32_t* a, const uint32_t* b)
{
    asm volatile(
        "mma.sync.aligned.m16n8k16.row.col.f32.bf16.bf16.f32 "
        "{%0,%1,%2,%3}, {%4,%5,%6,%7}, {%8,%9}, {%0,%1,%2,%3};"
        : "+f"(c[0]), "+f"(c[1]), "+f"(c[2]), "+f"(c[3])
        : "r"(a[0]), "r"(a[1]), "r"(a[2]), "r"(a[3]), "r"(b[0]), "r"(b[1]));
}

__device__ __forceinline__ void cp_async16(uint32_t smem, const void* gmem)
{
    asm volatile("cp.async.cg.shared.global [%0], [%1], 16;" :: "r"(smem), "l"(gmem));
}
#define CP_COMMIT()  asm volatile("cp.async.commit_group;")
#define CP_WAIT(n)   asm volatile("cp.async.wait_group %0;" :: "n"(n))

template<int EPI, int LNM>
__global__ __launch_bounds__(256, 1) void mma_gemm_kernel(
    const float* __restrict__ A,
    const __nv_bfloat16* __restrict__ Bhi, const __nv_bfloat16* __restrict__ Blo,
    const float* __restrict__ bias, float* __restrict__ Cout,
    const float* __restrict__ resid,
    const float2* __restrict__ stats,
    const float* __restrict__ lng, const float* __restrict__ lnb,
    int N, int K, int shifted)
{
    extern __shared__ __nv_bfloat16 sm[];
    uint32_t smbase = (uint32_t)__cvta_generic_to_shared(sm);
    int tid = threadIdx.x;
    int wid = tid >> 5, lane = tid & 31;
    int wr = wid >> 2, wc = wid & 3;            // warp grid 2x4
    int g = lane >> 2, t2 = (lane & 3) * 2;
    int m0 = blockIdx.y * 128, n0 = blockIdx.x * BN;

    // ---- A source row mapping (one row per 2 threads) ----
    int ar = tid >> 1, ahf = tid & 1;
    size_t tok;
    {
        int m = m0 + ar;
        if (LNM == 2) {
            int win = m / NTOK, n = m - win * NTOK;
            int b = win >> 6, wl = win & 63;
            int hs = (wl >> 3) * WSZ + n / WSZ;
            int ws = (wl & 7)  * WSZ + n % WSZ;
            if (shifted) { hs = (hs + SSHIFT) % HH; ws = (ws + SSHIFT) % WW2; }
            tok = ((size_t)b * HH + hs) * WW2 + ws;
        } else {
            tok = (size_t)m;
        }
    }
    float mu = 0.f, rstd = 1.f;
    if (LNM) { float2 st = stats[tok]; mu = st.x; rstd = st.y; }
    const float* Ap = A + tok * K + ahf * 16;

    // ---- B cp.async assignments: 768 hi chunks + 768 lo chunks of 16B ----
    int brow = tid >> 2, bq = tid & 3;          // rows brow, brow+64, brow+128
    const __nv_bfloat16* myBh = Bhi + (size_t)(n0 + brow) * K + bq * 8;
    const __nv_bfloat16* myBl = Blo + (size_t)(n0 + brow) * K + bq * 8;
    uint32_t myBsmH = smbase + 2 * (OFF_BHI + brow * STRD + bq * 8);
    uint32_t myBsmL = smbase + 2 * (OFF_BLO + brow * STRD + bq * 8);
    const size_t bgstep = (size_t)64 * K;       // 64 rows
    const uint32_t bsstep = 2 * 64 * STRD;

    float acc[4][6][4];
    #pragma unroll
    for (int mt = 0; mt < 4; mt++)
        #pragma unroll
        for (int nt = 0; nt < 6; nt++)
            #pragma unroll
            for (int r = 0; r < 4; r++) acc[mt][nt][r] = 0.f;

    // prologue: issue B(0); prefetch A(0) regs
    #pragma unroll
    for (int i = 0; i < 3; i++) {
        cp_async16(myBsmH + i * bsstep, myBh + i * bgstep);
        cp_async16(myBsmL + i * bsstep, myBl + i * bgstep);
    }
    CP_COMMIT();
    float pa[16];
    #pragma unroll
    for (int j4 = 0; j4 < 4; j4++)
        *(float4*)&pa[j4 * 4] = *(const float4*)(Ap + j4 * 4);

    int KT = K >> 5;
    for (int kt = 0; kt < KT; kt++) {
        __nv_bfloat16* st = sm + (kt & 1) * STAGE;
        // ---- STS A (optional LN) ----
        {
            float f[16];
            if (LNM) {
                int c0 = kt * 32 + ahf * 16;
                float lg[16], lb2[16];
                #pragma unroll
                for (int j4 = 0; j4 < 4; j4++) {
                    *(float4*)&lg[j4 * 4]  = *(const float4*)(lng + c0 + j4 * 4);
                    *(float4*)&lb2[j4 * 4] = *(const float4*)(lnb + c0 + j4 * 4);
                }
                #pragma unroll
                for (int j = 0; j < 16; j++)
                    f[j] = (pa[j] - mu) * rstd * lg[j] + lb2[j];
            } else {
                #pragma unroll
                for (int j = 0; j < 16; j++) f[j] = pa[j];
            }
            uint4 h0, l0, h1, l1;
            split8(f, h0, l0);
            split8(f + 8, h1, l1);
            uint4* dh = (uint4*)&st[OFF_AHI + ar * STRD + ahf * 16];
            uint4* dl = (uint4*)&st[OFF_ALO + ar * STRD + ahf * 16];
            dh[0] = h0; dh[1] = h1;
            dl[0] = l0; dl[1] = l1;
        }
        // issue B(kt+1) before waiting on B(kt)
        if (kt + 1 < KT) {
            uint32_t so = ((kt + 1) & 1) * (2 * STAGE);
            int ko = (kt + 1) * 32;
            #pragma unroll
            for (int i = 0; i < 3; i++) {
                cp_async16(myBsmH + so + i * bsstep, myBh + ko + i * bgstep);
                cp_async16(myBsmL + so + i * bsstep, myBl + ko + i * bgstep);
            }
            CP_COMMIT();
            CP_WAIT(1);
        } else {
            CP_WAIT(0);
        }
        __syncthreads();
        // prefetch A(kt+1) regs
        if (kt + 1 < KT) {
            const float* ap2 = Ap + (kt + 1) * 32;
            #pragma unroll
            for (int j4 = 0; j4 < 4; j4++)
                *(float4*)&pa[j4 * 4] = *(const float4*)(ap2 + j4 * 4);
        }
        // ---- compute ----
        const __nv_bfloat16* cs = sm + (kt & 1) * STAGE;
        #pragma unroll
        for (int kk = 0; kk < 32; kk += 16) {
            uint32_t Ah[4][4], Bh[6][2];
            #pragma unroll
            for (int mt = 0; mt < 4; mt++) {
                int r0 = (wr * 64 + mt * 16 + g) * STRD + kk + t2;
                Ah[mt][0] = *(const uint32_t*)&cs[OFF_AHI + r0];
                Ah[mt][1] = *(const uint32_t*)&cs[OFF_AHI + r0 + 8 * STRD];
                Ah[mt][2] = *(const uint32_t*)&cs[OFF_AHI + r0 + 8];
                Ah[mt][3] = *(const uint32_t*)&cs[OFF_AHI + r0 + 8 * STRD + 8];
            }
            #pragma unroll
            for (int nt = 0; nt < 6; nt++) {
                int rb = (wc * 48 + nt * 8 + g) * STRD + kk + t2;
                Bh[nt][0] = *(const uint32_t*)&cs[OFF_BHI + rb];
                Bh[nt][1] = *(const uint32_t*)&cs[OFF_BHI + rb + 8];
            }
            #pragma unroll
            for (int mt = 0; mt < 4; mt++)
                #pragma unroll
                for (int nt = 0; nt < 6; nt++)
                    mma16816(acc[mt][nt], Ah[mt], Bh[nt]);
            {
                uint32_t Al[4][4];
                #pragma unroll
                for (int mt = 0; mt < 4; mt++) {
                    int r0 = (wr * 64 + mt * 16 + g) * STRD + kk + t2;
                    Al[mt][0] = *(const uint32_t*)&cs[OFF_ALO + r0];
                    Al[mt][1] = *(const uint32_t*)&cs[OFF_ALO + r0 + 8 * STRD];
                    Al[mt][2] = *(const uint32_t*)&cs[OFF_ALO + r0 + 8];
                    Al[mt][3] = *(const uint32_t*)&cs[OFF_ALO + r0 + 8 * STRD + 8];
                }
                #pragma unroll
                for (int mt = 0; mt < 4; mt++)
                    #pragma unroll
                    for (int nt = 0; nt < 6; nt++)
                        mma16816(acc[mt][nt], Al[mt], Bh[nt]);
            }
            {
                uint32_t Bl[6][2];
                #pragma unroll
                for (int nt = 0; nt < 6; nt++) {
                    int rb = (wc * 48 + nt * 8 + g) * STRD + kk + t2;
                    Bl[nt][0] = *(const uint32_t*)&cs[OFF_BLO + rb];
                    Bl[nt][1] = *(const uint32_t*)&cs[OFF_BLO + rb + 8];
                }
                #pragma unroll
                for (int mt = 0; mt < 4; mt++)
                    #pragma unroll
                    for (int nt = 0; nt < 6; nt++)
                        mma16816(acc[mt][nt], Ah[mt], Bl[nt]);
            }
        }
        __syncthreads();
    }

    // ---- epilogue ----
    #pragma unroll
    for (int mt = 0; mt < 4; mt++) {
        #pragma unroll
        for (int hf = 0; hf < 2; hf++) {
            int m = m0 + wr * 64 + mt * 16 + hf * 8 + g;
            size_t orow;
            if (EPI == 1) {
                int win = m / NTOK, n = m - win * NTOK;
                int b = win >> 6, wl = win & 63;
                int hs = (wl >> 3) * WSZ + n / WSZ;
                int ws = (wl & 7)  * WSZ + n % WSZ;
                if (shifted) { hs = (hs + SSHIFT) % HH; ws = (ws + SSHIFT) % WW2; }
                orow = (((size_t)b * HH + hs) * WW2 + ws) * CC;
            } else if (EPI == 3) {
                orow = (size_t)m * CC;
            } else {
                orow = (size_t)m * N;
            }
            #pragma unroll
            for (int nt = 0; nt < 6; nt++) {
                int n = n0 + wc * 48 + nt * 8 + t2;
                float vx = acc[mt][nt][hf * 2 + 0] + bias[n];
                float vy = acc[mt][nt][hf * 2 + 1] + bias[n + 1];
                if (EPI == 2) {
                    vx = 0.5f * vx * (1.f + erff(vx * 0.70710678118654752f));
                    vy = 0.5f * vy * (1.f + erff(vy * 0.70710678118654752f));
                }
                if (EPI == 0 || EPI == 2) {
                    float2 v = {vx, vy};
                    *(float2*)&Cout[orow + n] = v;
                } else {
                    float2 r = *(const float2*)&resid[orow + n];
                    float2 v = {r.x + vx, r.y + vy};
                    *(float2*)&Cout[orow + n] = v;
                }
            }
        }
    }
}

// ====================== launch ======================
extern "C" void kernel_launch(void* const* d_in, const int* in_sizes, int n_in,
                              void* d_out, int out_size)
{
    (void)in_sizes; (void)n_in; (void)out_size;
    const float* x     = (const float*)d_in[0];
    const float* ln1g  = (const float*)d_in[1];
    const float* ln1b  = (const float*)d_in[2];
    const float* qkvw  = (const float*)d_in[3];
    const float* qkvb  = (const float*)d_in[4];
    const float* rpb   = (const float*)d_in[5];
    const float* projw = (const float*)d_in[6];
    const float* projb = (const float*)d_in[7];
    const float* ln2g  = (const float*)d_in[8];
    const float* ln2b  = (const float*)d_in[9];
    const float* fc1w  = (const float*)d_in[10];
    const float* fc1b  = (const float*)d_in[11];
    const float* fc2w  = (const float*)d_in[12];
    const float* fc2b  = (const float*)d_in[13];
    float* out = (float*)d_out;

    float *X, *XW, *QKV, *H1; float2* ST;
    cudaGetSymbolAddress((void**)&X,   g_X);
    cudaGetSymbolAddress((void**)&XW,  g_XW);
    cudaGetSymbolAddress((void**)&QKV, g_QKV);
    cudaGetSymbolAddress((void**)&H1,  g_H1);
    cudaGetSymbolAddress((void**)&ST,  g_ST);

    __nv_bfloat16 *Wqh, *Wql, *Wph, *Wpl, *W1h, *W1l, *W2h, *W2l;
    cudaGetSymbolAddress((void**)&Wqh, g_Wqkv_h); cudaGetSymbolAddress((void**)&Wql, g_Wqkv_l);
    cudaGetSymbolAddress((void**)&Wph, g_Wprj_h); cudaGetSymbolAddress((void**)&Wpl, g_Wprj_l);
    cudaGetSymbolAddress((void**)&W1h, g_Wfc1_h); cudaGetSymbolAddress((void**)&W1l, g_Wfc1_l);
    cudaGetSymbolAddress((void**)&W2h, g_Wfc2_h); cudaGetSymbolAddress((void**)&W2l, g_Wfc2_l);

    cudaFuncSetAttribute(mma_gemm_kernel<0,2>, cudaFuncAttributeMaxDynamicSharedMemorySize, GSMEM);
    cudaFuncSetAttribute(mma_gemm_kernel<1,0>, cudaFuncAttributeMaxDynamicSharedMemorySize, GSMEM);
    cudaFuncSetAttribute(mma_gemm_kernel<2,1>, cudaFuncAttributeMaxDynamicSharedMemorySize, GSMEM);
    cudaFuncSetAttribute(mma_gemm_kernel<3,0>, cudaFuncAttributeMaxDynamicSharedMemorySize, GSMEM);

    // weight transpose + hi/lo split (one launch per layer)
    for (int layer = 0; layer < 2; layer++) {
        size_t oq = (size_t)layer * 192 * 576;
        size_t op = (size_t)layer * 192 * 192;
        size_t o1 = (size_t)layer * 192 * 768;
        size_t o2 = (size_t)layer * 768 * 192;
        wsplit_layer_kernel<<<1728, 256>>>(
            qkvw + oq, projw + op, fc1w + o1, fc2w + o2,
            Wqh + oq, Wql + oq, Wph + op, Wpl + op,
            W1h + o1, W1l + o1, W2h + o2, W2l + o2);
    }

    const int MB = TTOT / 128;  // 1568
    for (int layer = 0; layer < 2; layer++) {
        int shifted = layer & 1;
        size_t oq = (size_t)layer * 192 * 576;
        size_t op = (size_t)layer * 192 * 192;
        size_t o1 = (size_t)layer * 192 * 768;
        size_t o2 = (size_t)layer * 768 * 192;
        const float* pre = (layer == 0) ? x : X;   // pre-LN1 residual stream
        float* fc2_out   = (layer == 0) ? X : out; // final layer writes d_out

        lnstats_kernel<<<TTOT / 8, 256>>>(pre, ST);
        // QKV: LN + window(+shift) gather fused
        mma_gemm_kernel<0, 2><<<dim3(576 / BN, MB), 256, GSMEM>>>(
            pre, Wqh + oq, Wql + oq, qkvb + layer * 576, QKV,
            nullptr, ST, ln1g + layer * CC, ln1b + layer * CC, 576, 192, shifted);
        attn_kernel<<<NWINS * NHEADS, 128>>>(QKV, XW, rpb + layer * 169 * NHEADS, shifted);
        // proj + window-reverse(+unshift) + residual
        mma_gemm_kernel<1, 0><<<dim3(1, MB), 256, GSMEM>>>(
            XW, Wph + op, Wpl + op, projb + layer * CC, X,
            pre, nullptr, nullptr, nullptr, 192, 192, shifted);
        lnstats_kernel<<<TTOT / 8, 256>>>(X, ST);
        // fc1 + GELU, LN fused
        mma_gemm_kernel<2, 1><<<dim3(768 / BN, MB), 256, GSMEM>>>(
            X, W1h + o1, W1l + o1, fc1b + layer * HIDDIM, H1,
            nullptr, ST, ln2g + layer * CC, ln2b + layer * CC, 768, 192, 0);
        // fc2 + residual (layer1 writes d_out)
        mma_gemm_kernel<3, 0><<<dim3(1, MB), 256, GSMEM>>>(
            H1, W2h + o2, W2l + o2, fc2b + layer * CC, fc2_out,
            X, nullptr, nullptr, nullptr, 192, 768, 0);
    }
}

// round 9
// speedup vs baseline: 1.5411x; 1.5411x over previous
#include <cuda_runtime.h>
#include <cuda_bf16.h>
#include <math.h>
#include <cstdint>

// ---------------- problem constants ----------------
#define HH      56
#define WW2     56
#define CC      192
#define NHEADS  6
#define WSZ     7
#define SSHIFT  3
#define HIDDIM  768
#define NTOK    49
#define HDIM    32
#define NWINS   4096
#define TTOT    200704
#define SCALEQ  0.17677669529663687f

// ---------------- scratch ----------------
__device__ float g_X  [(size_t)TTOT * CC];          // residual stream fp32
__device__ float g_QKV[(size_t)TTOT * 3 * CC];      // qkv fp32 (window order)
__device__ __nv_bfloat16 g_Ah [(size_t)TTOT * CC];      // activation hi (GEMM A)
__device__ __nv_bfloat16 g_Al [(size_t)TTOT * CC];      // activation lo
__device__ __nv_bfloat16 g_H1h[(size_t)TTOT * HIDDIM];  // MLP hidden hi
__device__ __nv_bfloat16 g_H1l[(size_t)TTOT * HIDDIM];  // MLP hidden lo

// split weights, transposed to [N][K] bf16 (hi + lo)
__device__ __nv_bfloat16 g_Wqkv_h[2 * 576 * 192];
__device__ __nv_bfloat16 g_Wqkv_l[2 * 576 * 192];
__device__ __nv_bfloat16 g_Wprj_h[2 * 192 * 192];
__device__ __nv_bfloat16 g_Wprj_l[2 * 192 * 192];
__device__ __nv_bfloat16 g_Wfc1_h[2 * 768 * 192];
__device__ __nv_bfloat16 g_Wfc1_l[2 * 768 * 192];
__device__ __nv_bfloat16 g_Wfc2_h[2 * 192 * 768];
__device__ __nv_bfloat16 g_Wfc2_l[2 * 192 * 768];

// ====================== weight transpose + split (one layer) ======================
__global__ __launch_bounds__(256) void wsplit_layer_kernel(
    const float* __restrict__ qkvw, const float* __restrict__ projw,
    const float* __restrict__ fc1w, const float* __restrict__ fc2w,
    __nv_bfloat16* __restrict__ qh, __nv_bfloat16* __restrict__ ql,
    __nv_bfloat16* __restrict__ ph, __nv_bfloat16* __restrict__ pl,
    __nv_bfloat16* __restrict__ f1h, __nv_bfloat16* __restrict__ f1l,
    __nv_bfloat16* __restrict__ f2h, __nv_bfloat16* __restrict__ f2l)
{
    int idx = blockIdx.x * 256 + threadIdx.x;
    const float* W; __nv_bfloat16 *Hp, *Lp; int K, N, off;
    if (idx < 110592)       { W = qkvw; Hp = qh;  Lp = ql;  K = 192; N = 576; off = idx; }
    else if (idx < 147456)  { W = projw; Hp = ph; Lp = pl;  K = 192; N = 192; off = idx - 110592; }
    else if (idx < 294912)  { W = fc1w; Hp = f1h; Lp = f1l; K = 192; N = 768; off = idx - 147456; }
    else if (idx < 442368)  { W = fc2w; Hp = f2h; Lp = f2l; K = 768; N = 192; off = idx - 294912; }
    else return;
    int k = off / N, n = off - k * N;
    float v = W[off];
    __nv_bfloat16 h = __float2bfloat16_rn(v);
    __nv_bfloat16 l = __float2bfloat16_rn(v - __bfloat162float(h));
    Hp[(size_t)n * K + k] = h;
    Lp[(size_t)n * K + k] = l;
}

// ====================== LN + (optional window gather) + hi/lo split ======================
// one warp per OUTPUT row m; writes bf16 hi/lo rows in GEMM-A order
__global__ __launch_bounds__(256) void lnsplit_kernel(
    const float* __restrict__ src,
    __nv_bfloat16* __restrict__ oh, __nv_bfloat16* __restrict__ ol,
    const float* __restrict__ g, const float* __restrict__ bta,
    int gather, int shifted)
{
    int warp = threadIdx.x >> 5, lane = threadIdx.x & 31;
    int m = blockIdx.x * 8 + warp;
    size_t tok;
    if (gather) {
        int win = m / NTOK, n = m - win * NTOK;
        int b = win >> 6, wl = win & 63;
        int hs = (wl >> 3) * WSZ + n / WSZ;
        int ws = (wl & 7)  * WSZ + n % WSZ;
        if (shifted) { hs = (hs + SSHIFT) % HH; ws = (ws + SSHIFT) % WW2; }
        tok = ((size_t)b * HH + hs) * WW2 + ws;
    } else {
        tok = (size_t)m;
    }
    const float* xp = src + tok * CC;
    float v[6]; float s = 0.f, ss = 0.f;
    #pragma unroll
    for (int j = 0; j < 6; j++) { v[j] = xp[lane + 32*j]; s += v[j]; ss += v[j]*v[j]; }
    #pragma unroll
    for (int o = 16; o > 0; o >>= 1) {
        s  += __shfl_xor_sync(0xffffffffu, s,  o);
        ss += __shfl_xor_sync(0xffffffffu, ss, o);
    }
    float mu = s * (1.f / CC);
    float rstd = rsqrtf(ss * (1.f / CC) - mu * mu + 1e-5f);
    __nv_bfloat16* ophi = oh + (size_t)m * CC;
    __nv_bfloat16* oplo = ol + (size_t)m * CC;
    #pragma unroll
    for (int j = 0; j < 6; j++) {
        int c = lane + 32*j;
        float f = (v[j] - mu) * rstd * g[c] + bta[c];
        __nv_bfloat16 h = __float2bfloat16_rn(f);
        ophi[c] = h;
        oplo[c] = __float2bfloat16_rn(f - __bfloat162float(h));
    }
}

// ====================== window attention (writes bf16 hi/lo out) ======================
__global__ __launch_bounds__(128) void attn_kernel(
    const float* __restrict__ qkv,
    __nv_bfloat16* __restrict__ oh, __nv_bfloat16* __restrict__ ol,
    const float* __restrict__ rpb, int shifted)
{
    int win = blockIdx.x / NHEADS;
    int hd  = blockIdx.x % NHEADS;
    __shared__ float q[NTOK][HDIM + 1];
    __shared__ float k[NTOK][HDIM + 1];
    __shared__ float v[NTOK][HDIM + 1];
    __shared__ float sc[NTOK][52];
    __shared__ int   lab[NTOK];
    int tid = threadIdx.x;

    const float* base = qkv + (size_t)win * NTOK * 576 + hd * HDIM;
    for (int idx = tid; idx < NTOK * HDIM; idx += 128) {
        int i = idx >> 5, d = idx & 31;
        const float* row = base + (size_t)i * 576 + d;
        q[i][d] = row[0]   * SCALEQ;
        k[i][d] = row[192];
        v[i][d] = row[384];
    }
    if (shifted && tid < NTOK) {
        int wl = win & 63;
        int h = (wl >> 3) * WSZ + tid / WSZ;
        int w = (wl & 7)  * WSZ + tid % WSZ;
        int rc = (h < HH  - WSZ) ? 0 : ((h < HH  - SSHIFT) ? 1 : 2);
        int cc = (w < WW2 - WSZ) ? 0 : ((w < WW2 - SSHIFT) ? 1 : 2);
        lab[tid] = rc * 3 + cc;
    }
    __syncthreads();

    for (int idx = tid; idx < NTOK * NTOK; idx += 128) {
        int i = idx / NTOK, j = idx - i * NTOK;
        float acc = 0.f;
        #pragma unroll
        for (int d = 0; d < HDIM; d++) acc += q[i][d] * k[j][d];
        int ridx = (i / WSZ - j / WSZ + WSZ - 1) * (2 * WSZ - 1)
                 + (i % WSZ - j % WSZ + WSZ - 1);
        acc += rpb[ridx * NHEADS + hd];
        if (shifted && lab[i] != lab[j]) acc -= 100.f;
        sc[i][j] = acc;
    }
    __syncthreads();

    int warp = tid >> 5, lane = tid & 31;
    for (int i = warp; i < NTOK; i += 4) {
        float a0 = (lane < NTOK)      ? sc[i][lane]      : -1e30f;
        float a1 = (lane + 32 < NTOK) ? sc[i][lane + 32] : -1e30f;
        float mx = fmaxf(a0, a1);
        #pragma unroll
        for (int o = 16; o > 0; o >>= 1) mx = fmaxf(mx, __shfl_xor_sync(0xffffffffu, mx, o));
        float e0 = (lane < NTOK)      ? __expf(a0 - mx) : 0.f;
        float e1 = (lane + 32 < NTOK) ? __expf(a1 - mx) : 0.f;
        float sum = e0 + e1;
        #pragma unroll
        for (int o = 16; o > 0; o >>= 1) sum += __shfl_xor_sync(0xffffffffu, sum, o);
        float inv = 1.f / sum;
        if (lane < NTOK)      sc[i][lane]      = e0 * inv;
        if (lane + 32 < NTOK) sc[i][lane + 32] = e1 * inv;
    }
    __syncthreads();

    size_t ob = (size_t)win * NTOK * CC + hd * HDIM;
    for (int idx = tid; idx < NTOK * HDIM; idx += 128) {
        int i = idx >> 5, d = idx & 31;
        float acc = 0.f;
        #pragma unroll
        for (int j = 0; j < NTOK; j++) acc += sc[i][j] * v[j][d];
        __nv_bfloat16 h = __float2bfloat16_rn(acc);
        oh[ob + (size_t)i * CC + d] = h;
        ol[ob + (size_t)i * CC + d] = __float2bfloat16_rn(acc - __bfloat162float(h));
    }
}

// ====================== pure bf16 hi/lo GEMM, fully async pipeline ======================
// C[M,N] = (Ah+Al)[M,K] @ (Bh+Bl)[N,K]^T + bias, 3-pass hi/lo.
// CTA 128x64, warp grid 4x2, warp tile 32x32, BK=32, 3-stage cp.async pipeline.
// EPI: 0 fp32 store; 1 win-reverse(+unshift) residual; 2 GELU -> bf16 hi/lo store; 3 residual
#define NSTG    3
#define STRD    40
#define OFF_AH  0
#define OFF_AL  5120
#define OFF_BH  10240
#define OFF_BL  12800
#define STAGE   15360
#define GSMEM   (NSTG * STAGE * 2)   // 92160 bytes

__device__ __forceinline__ void mma16816(float* c, const uint32_t* a, const uint32_t* b)
{
    asm volatile(
        "mma.sync.aligned.m16n8k16.row.col.f32.bf16.bf16.f32 "
        "{%0,%1,%2,%3}, {%4,%5,%6,%7}, {%8,%9}, {%0,%1,%2,%3};"
        : "+f"(c[0]), "+f"(c[1]), "+f"(c[2]), "+f"(c[3])
        : "r"(a[0]), "r"(a[1]), "r"(a[2]), "r"(a[3]), "r"(b[0]), "r"(b[1]));
}
__device__ __forceinline__ void cp_async16(uint32_t smem, const void* gmem)
{
    asm volatile("cp.async.cg.shared.global [%0], [%1], 16;" :: "r"(smem), "l"(gmem));
}
#define CP_COMMIT()  asm volatile("cp.async.commit_group;")
#define CP_WAIT(n)   asm volatile("cp.async.wait_group %0;" :: "n"(n))

template<int EPI>
__global__ __launch_bounds__(256, 2) void gemm_bf16_kernel(
    const __nv_bfloat16* __restrict__ Ah, const __nv_bfloat16* __restrict__ Al,
    const __nv_bfloat16* __restrict__ Bh, const __nv_bfloat16* __restrict__ Bl,
    const float* __restrict__ bias, float* __restrict__ Cout,
    const float* __restrict__ resid,
    __nv_bfloat16* __restrict__ OutH, __nv_bfloat16* __restrict__ OutL,
    int N, int K, int shifted)
{
    extern __shared__ __nv_bfloat16 sm[];
    uint32_t smb = (uint32_t)__cvta_generic_to_shared(sm);
    int tid = threadIdx.x;
    int wid = tid >> 5, lane = tid & 31;
    int wr = wid >> 1, wc = wid & 1;          // 4x2 warp grid
    int g = lane >> 2, t2 = (lane & 3) * 2;
    int m0 = blockIdx.y * 128, n0 = blockIdx.x * 64;

    // loader: A 512 16B-chunks per part (2/thread), B 256 per part (1/thread)
    int arow = tid >> 1, aq = (tid & 1) * 2;  // chunks aq, aq+1
    int brow = tid >> 2, bq = tid & 3;
    const __nv_bfloat16* gAh = Ah + (size_t)(m0 + arow) * K + aq * 8;
    const __nv_bfloat16* gAl = Al + (size_t)(m0 + arow) * K + aq * 8;
    const __nv_bfloat16* gBh = Bh + (size_t)(n0 + brow) * K + bq * 8;
    const __nv_bfloat16* gBl = Bl + (size_t)(n0 + brow) * K + bq * 8;
    uint32_t sAh = smb + 2 * (OFF_AH + arow * STRD + aq * 8);
    uint32_t sAl = smb + 2 * (OFF_AL + arow * STRD + aq * 8);
    uint32_t sBh = smb + 2 * (OFF_BH + brow * STRD + bq * 8);
    uint32_t sBl = smb + 2 * (OFF_BL + brow * STRD + bq * 8);

    auto issue = [&](int kt) {
        uint32_t so = 2u * (uint32_t)((kt % NSTG) * STAGE);
        int ko = kt * 32;
        cp_async16(sAh + so,      gAh + ko);
        cp_async16(sAh + so + 16, gAh + ko + 8);
        cp_async16(sAl + so,      gAl + ko);
        cp_async16(sAl + so + 16, gAl + ko + 8);
        cp_async16(sBh + so,      gBh + ko);
        cp_async16(sBl + so,      gBl + ko);
        CP_COMMIT();
    };

    float acc[2][4][4];
    #pragma unroll
    for (int mt = 0; mt < 2; mt++)
        #pragma unroll
        for (int nt = 0; nt < 4; nt++)
            #pragma unroll
            for (int r = 0; r < 4; r++) acc[mt][nt][r] = 0.f;

    int KT = K >> 5;
    issue(0);
    if (KT > 1) issue(1);

    for (int kt = 0; kt < KT; kt++) {
        CP_WAIT(1);
        __syncthreads();
        if (kt + 2 < KT) issue(kt + 2);
        const __nv_bfloat16* cs = sm + (kt % NSTG) * STAGE;
        #pragma unroll
        for (int kk = 0; kk < 32; kk += 16) {
            uint32_t Afh[2][4], Bfh[4][2];
            #pragma unroll
            for (int mt = 0; mt < 2; mt++) {
                int r0 = (wr * 32 + mt * 16 + g) * STRD + kk + t2;
                Afh[mt][0] = *(const uint32_t*)&cs[OFF_AH + r0];
                Afh[mt][1] = *(const uint32_t*)&cs[OFF_AH + r0 + 8 * STRD];
                Afh[mt][2] = *(const uint32_t*)&cs[OFF_AH + r0 + 8];
                Afh[mt][3] = *(const uint32_t*)&cs[OFF_AH + r0 + 8 * STRD + 8];
            }
            #pragma unroll
            for (int nt = 0; nt < 4; nt++) {
                int rb = (wc * 32 + nt * 8 + g) * STRD + kk + t2;
                Bfh[nt][0] = *(const uint32_t*)&cs[OFF_BH + rb];
                Bfh[nt][1] = *(const uint32_t*)&cs[OFF_BH + rb + 8];
            }
            #pragma unroll
            for (int mt = 0; mt < 2; mt++)
                #pragma unroll
                for (int nt = 0; nt < 4; nt++)
                    mma16816(acc[mt][nt], Afh[mt], Bfh[nt]);
            {
                uint32_t Afl[2][4];
                #pragma unroll
                for (int mt = 0; mt < 2; mt++) {
                    int r0 = (wr * 32 + mt * 16 + g) * STRD + kk + t2;
                    Afl[mt][0] = *(const uint32_t*)&cs[OFF_AL + r0];
                    Afl[mt][1] = *(const uint32_t*)&cs[OFF_AL + r0 + 8 * STRD];
                    Afl[mt][2] = *(const uint32_t*)&cs[OFF_AL + r0 + 8];
                    Afl[mt][3] = *(const uint32_t*)&cs[OFF_AL + r0 + 8 * STRD + 8];
                }
                #pragma unroll
                for (int mt = 0; mt < 2; mt++)
                    #pragma unroll
                    for (int nt = 0; nt < 4; nt++)
                        mma16816(acc[mt][nt], Afl[mt], Bfh[nt]);
            }
            {
                uint32_t Bfl[4][2];
                #pragma unroll
                for (int nt = 0; nt < 4; nt++) {
                    int rb = (wc * 32 + nt * 8 + g) * STRD + kk + t2;
                    Bfl[nt][0] = *(const uint32_t*)&cs[OFF_BL + rb];
                    Bfl[nt][1] = *(const uint32_t*)&cs[OFF_BL + rb + 8];
                }
                #pragma unroll
                for (int mt = 0; mt < 2; mt++)
                    #pragma unroll
                    for (int nt = 0; nt < 4; nt++)
                        mma16816(acc[mt][nt], Afh[mt], Bfl[nt]);
            }
        }
        __syncthreads();
    }

    // ---- epilogue ----
    #pragma unroll
    for (int mt = 0; mt < 2; mt++) {
        #pragma unroll
        for (int hf = 0; hf < 2; hf++) {
            int m = m0 + wr * 32 + mt * 16 + hf * 8 + g;
            size_t orow;
            if (EPI == 1) {
                int win = m / NTOK, n = m - win * NTOK;
                int b = win >> 6, wl = win & 63;
                int hs = (wl >> 3) * WSZ + n / WSZ;
                int ws = (wl & 7)  * WSZ + n % WSZ;
                if (shifted) { hs = (hs + SSHIFT) % HH; ws = (ws + SSHIFT) % WW2; }
                orow = (((size_t)b * HH + hs) * WW2 + ws) * CC;
            } else if (EPI == 3) {
                orow = (size_t)m * CC;
            } else {
                orow = (size_t)m * N;
            }
            #pragma unroll
            for (int nt = 0; nt < 4; nt++) {
                int n = n0 + wc * 32 + nt * 8 + t2;
                float vx = acc[mt][nt][hf * 2 + 0] + bias[n];
                float vy = acc[mt][nt][hf * 2 + 1] + bias[n + 1];
                if (EPI == 2) {
                    vx = 0.5f * vx * (1.f + erff(vx * 0.70710678118654752f));
                    vy = 0.5f * vy * (1.f + erff(vy * 0.70710678118654752f));
                    __nv_bfloat16 hx = __float2bfloat16_rn(vx);
                    __nv_bfloat16 hy = __float2bfloat16_rn(vy);
                    __nv_bfloat162 hp; hp.x = hx; hp.y = hy;
                    __nv_bfloat162 lp;
                    lp.x = __float2bfloat16_rn(vx - __bfloat162float(hx));
                    lp.y = __float2bfloat16_rn(vy - __bfloat162float(hy));
                    *(__nv_bfloat162*)&OutH[orow + n] = hp;
                    *(__nv_bfloat162*)&OutL[orow + n] = lp;
                } else if (EPI == 0) {
                    float2 v = {vx, vy};
                    *(float2*)&Cout[orow + n] = v;
                } else {
                    float2 r = *(const float2*)&resid[orow + n];
                    float2 v = {r.x + vx, r.y + vy};
                    *(float2*)&Cout[orow + n] = v;
                }
            }
        }
    }
}

// ====================== launch ======================
extern "C" void kernel_launch(void* const* d_in, const int* in_sizes, int n_in,
                              void* d_out, int out_size)
{
    (void)in_sizes; (void)n_in; (void)out_size;
    const float* x     = (const float*)d_in[0];
    const float* ln1g  = (const float*)d_in[1];
    const float* ln1b  = (const float*)d_in[2];
    const float* qkvw  = (const float*)d_in[3];
    const float* qkvb  = (const float*)d_in[4];
    const float* rpb   = (const float*)d_in[5];
    const float* projw = (const float*)d_in[6];
    const float* projb = (const float*)d_in[7];
    const float* ln2g  = (const float*)d_in[8];
    const float* ln2b  = (const float*)d_in[9];
    const float* fc1w  = (const float*)d_in[10];
    const float* fc1b  = (const float*)d_in[11];
    const float* fc2w  = (const float*)d_in[12];
    const float* fc2b  = (const float*)d_in[13];
    float* out = (float*)d_out;

    float *X, *QKV;
    __nv_bfloat16 *Ah, *Al, *H1h, *H1l;
    cudaGetSymbolAddress((void**)&X,   g_X);
    cudaGetSymbolAddress((void**)&QKV, g_QKV);
    cudaGetSymbolAddress((void**)&Ah,  g_Ah);
    cudaGetSymbolAddress((void**)&Al,  g_Al);
    cudaGetSymbolAddress((void**)&H1h, g_H1h);
    cudaGetSymbolAddress((void**)&H1l, g_H1l);

    __nv_bfloat16 *Wqh, *Wql, *Wph, *Wpl, *W1h, *W1l, *W2h, *W2l;
    cudaGetSymbolAddress((void**)&Wqh, g_Wqkv_h); cudaGetSymbolAddress((void**)&Wql, g_Wqkv_l);
    cudaGetSymbolAddress((void**)&Wph, g_Wprj_h); cudaGetSymbolAddress((void**)&Wpl, g_Wprj_l);
    cudaGetSymbolAddress((void**)&W1h, g_Wfc1_h); cudaGetSymbolAddress((void**)&W1l, g_Wfc1_l);
    cudaGetSymbolAddress((void**)&W2h, g_Wfc2_h); cudaGetSymbolAddress((void**)&W2l, g_Wfc2_l);

    cudaFuncSetAttribute(gemm_bf16_kernel<0>, cudaFuncAttributeMaxDynamicSharedMemorySize, GSMEM);
    cudaFuncSetAttribute(gemm_bf16_kernel<1>, cudaFuncAttributeMaxDynamicSharedMemorySize, GSMEM);
    cudaFuncSetAttribute(gemm_bf16_kernel<2>, cudaFuncAttributeMaxDynamicSharedMemorySize, GSMEM);
    cudaFuncSetAttribute(gemm_bf16_kernel<3>, cudaFuncAttributeMaxDynamicSharedMemorySize, GSMEM);

    for (int layer = 0; layer < 2; layer++) {
        size_t oq = (size_t)layer * 192 * 576;
        size_t op = (size_t)layer * 192 * 192;
        size_t o1 = (size_t)layer * 192 * 768;
        size_t o2 = (size_t)layer * 768 * 192;
        wsplit_layer_kernel<<<1728, 256>>>(
            qkvw + oq, projw + op, fc1w + o1, fc2w + o2,
            Wqh + oq, Wql + oq, Wph + op, Wpl + op,
            W1h + o1, W1l + o1, W2h + o2, W2l + o2);
    }

    const int MB = TTOT / 128;  // 1568
    for (int layer = 0; layer < 2; layer++) {
        int shifted = layer & 1;
        size_t oq = (size_t)layer * 192 * 576;
        size_t op = (size_t)layer * 192 * 192;
        size_t o1 = (size_t)layer * 192 * 768;
        size_t o2 = (size_t)layer * 768 * 192;
        const float* pre = (layer == 0) ? x : X;   // pre-LN1 residual stream
        float* fc2_out   = (layer == 0) ? X : out; // last fc2 writes d_out

        // LN1 + window(+shift) gather + split -> Ah/Al
        lnsplit_kernel<<<TTOT / 8, 256>>>(pre, Ah, Al,
            ln1g + layer * CC, ln1b + layer * CC, 1, shifted);
        // QKV = A @ Wqkv + b  (fp32 store, window order)
        gemm_bf16_kernel<0><<<dim3(9, MB), 256, GSMEM>>>(
            Ah, Al, Wqh + oq, Wql + oq, qkvb + layer * 576, QKV,
            nullptr, nullptr, nullptr, 576, 192, 0);
        // attention -> Ah/Al (bf16 hi/lo, window order)
        attn_kernel<<<NWINS * NHEADS, 128>>>(QKV, Ah, Al, rpb + layer * 169 * NHEADS, shifted);
        // proj + window-reverse(+unshift) + residual -> X
        gemm_bf16_kernel<1><<<dim3(3, MB), 256, GSMEM>>>(
            Ah, Al, Wph + op, Wpl + op, projb + layer * CC, X,
            pre, nullptr, nullptr, 192, 192, shifted);
        // LN2 + split -> Ah/Al (token order)
        lnsplit_kernel<<<TTOT / 8, 256>>>(X, Ah, Al,
            ln2g + layer * CC, ln2b + layer * CC, 0, 0);
        // fc1 + GELU -> H1 hi/lo
        gemm_bf16_kernel<2><<<dim3(12, MB), 256, GSMEM>>>(
            Ah, Al, W1h + o1, W1l + o1, fc1b + layer * HIDDIM, nullptr,
            nullptr, H1h, H1l, 768, 192, 0);
        // fc2 + residual -> X / d_out
        gemm_bf16_kernel<3><<<dim3(3, MB), 256, GSMEM>>>(
            H1h, H1l, W2h + o2, W2l + o2, fc2b + layer * CC, fc2_out,
            X, nullptr, nullptr, 192, 768, 0);
    }
}

// round 10
// speedup vs baseline: 1.6784x; 1.0891x over previous
#include <cuda_runtime.h>
#include <cuda_bf16.h>
#include <math.h>
#include <cstdint>

// ---------------- problem constants ----------------
#define HH      56
#define WW2     56
#define CC      192
#define NHEADS  6
#define WSZ     7
#define SSHIFT  3
#define HIDDIM  768
#define NTOK    49
#define HDIM    32
#define NWINS   4096
#define TTOT    200704
#define SCALEQ  0.17677669529663687f

// ---------------- scratch ----------------
__device__ float g_X  [(size_t)TTOT * CC];          // residual stream fp32
__device__ float g_QKV[(size_t)TTOT * 3 * CC];      // qkv fp32 (window order)
__device__ __nv_bfloat16 g_Ah [(size_t)TTOT * CC];      // activation hi (GEMM A)
__device__ __nv_bfloat16 g_Al [(size_t)TTOT * CC];      // activation lo
__device__ __nv_bfloat16 g_H1h[(size_t)TTOT * HIDDIM];  // MLP hidden hi
__device__ __nv_bfloat16 g_H1l[(size_t)TTOT * HIDDIM];  // MLP hidden lo

// split weights, transposed to [N][K] bf16 (hi + lo)
__device__ __nv_bfloat16 g_Wqkv_h[2 * 576 * 192];
__device__ __nv_bfloat16 g_Wqkv_l[2 * 576 * 192];
__device__ __nv_bfloat16 g_Wprj_h[2 * 192 * 192];
__device__ __nv_bfloat16 g_Wprj_l[2 * 192 * 192];
__device__ __nv_bfloat16 g_Wfc1_h[2 * 768 * 192];
__device__ __nv_bfloat16 g_Wfc1_l[2 * 768 * 192];
__device__ __nv_bfloat16 g_Wfc2_h[2 * 192 * 768];
__device__ __nv_bfloat16 g_Wfc2_l[2 * 192 * 768];

// ====================== weight transpose + split (one layer) ======================
__global__ __launch_bounds__(256) void wsplit_layer_kernel(
    const float* __restrict__ qkvw, const float* __restrict__ projw,
    const float* __restrict__ fc1w, const float* __restrict__ fc2w,
    __nv_bfloat16* __restrict__ qh, __nv_bfloat16* __restrict__ ql,
    __nv_bfloat16* __restrict__ ph, __nv_bfloat16* __restrict__ pl,
    __nv_bfloat16* __restrict__ f1h, __nv_bfloat16* __restrict__ f1l,
    __nv_bfloat16* __restrict__ f2h, __nv_bfloat16* __restrict__ f2l)
{
    int idx = blockIdx.x * 256 + threadIdx.x;
    const float* W; __nv_bfloat16 *Hp, *Lp; int K, N, off;
    if (idx < 110592)       { W = qkvw; Hp = qh;  Lp = ql;  K = 192; N = 576; off = idx; }
    else if (idx < 147456)  { W = projw; Hp = ph; Lp = pl;  K = 192; N = 192; off = idx - 110592; }
    else if (idx < 294912)  { W = fc1w; Hp = f1h; Lp = f1l; K = 192; N = 768; off = idx - 147456; }
    else if (idx < 442368)  { W = fc2w; Hp = f2h; Lp = f2l; K = 768; N = 192; off = idx - 294912; }
    else return;
    int k = off / N, n = off - k * N;
    float v = W[off];
    __nv_bfloat16 h = __float2bfloat16_rn(v);
    __nv_bfloat16 l = __float2bfloat16_rn(v - __bfloat162float(h));
    Hp[(size_t)n * K + k] = h;
    Lp[(size_t)n * K + k] = l;
}

// ====================== LN + (optional window gather) + hi/lo split ======================
__global__ __launch_bounds__(256) void lnsplit_kernel(
    const float* __restrict__ src,
    __nv_bfloat16* __restrict__ oh, __nv_bfloat16* __restrict__ ol,
    const float* __restrict__ g, const float* __restrict__ bta,
    int gather, int shifted)
{
    int warp = threadIdx.x >> 5, lane = threadIdx.x & 31;
    int m = blockIdx.x * 8 + warp;
    size_t tok;
    if (gather) {
        int win = m / NTOK, n = m - win * NTOK;
        int b = win >> 6, wl = win & 63;
        int hs = (wl >> 3) * WSZ + n / WSZ;
        int ws = (wl & 7)  * WSZ + n % WSZ;
        if (shifted) { hs = (hs + SSHIFT) % HH; ws = (ws + SSHIFT) % WW2; }
        tok = ((size_t)b * HH + hs) * WW2 + ws;
    } else {
        tok = (size_t)m;
    }
    const float* xp = src + tok * CC;
    float v[6]; float s = 0.f, ss = 0.f;
    #pragma unroll
    for (int j = 0; j < 6; j++) { v[j] = xp[lane + 32*j]; s += v[j]; ss += v[j]*v[j]; }
    #pragma unroll
    for (int o = 16; o > 0; o >>= 1) {
        s  += __shfl_xor_sync(0xffffffffu, s,  o);
        ss += __shfl_xor_sync(0xffffffffu, ss, o);
    }
    float mu = s * (1.f / CC);
    float rstd = rsqrtf(ss * (1.f / CC) - mu * mu + 1e-5f);
    __nv_bfloat16* ophi = oh + (size_t)m * CC;
    __nv_bfloat16* oplo = ol + (size_t)m * CC;
    #pragma unroll
    for (int j = 0; j < 6; j++) {
        int c = lane + 32*j;
        float f = (v[j] - mu) * rstd * g[c] + bta[c];
        __nv_bfloat16 h = __float2bfloat16_rn(f);
        ophi[c] = h;
        oplo[c] = __float2bfloat16_rn(f - __bfloat162float(h));
    }
}

// ====================== window attention (register-blocked) ======================
__global__ __launch_bounds__(128) void attn_kernel(
    const float* __restrict__ qkv,
    __nv_bfloat16* __restrict__ oh, __nv_bfloat16* __restrict__ ol,
    const float* __restrict__ rpb, int shifted)
{
    int win = blockIdx.x / NHEADS;
    int hd  = blockIdx.x % NHEADS;
    __shared__ __align__(16) float q[52][33];
    __shared__ __align__(16) float k[52][33];
    __shared__ __align__(16) float v[52][36];
    __shared__ __align__(16) float sc[52][53];
    __shared__ int lab[52];
    int tid = threadIdx.x;

    const float* base = qkv + (size_t)win * NTOK * 576 + hd * HDIM;
    for (int idx = tid; idx < NTOK * HDIM; idx += 128) {
        int i = idx >> 5, d = idx & 31;
        const float* row = base + (size_t)i * 576 + d;
        q[i][d] = row[0]   * SCALEQ;
        k[i][d] = row[192];
        v[i][d] = row[384];
    }
    // zero padding rows 49..51
    for (int idx = tid; idx < 3 * 33; idx += 128) {
        q[49 + idx / 33][idx % 33] = 0.f;
        k[49 + idx / 33][idx % 33] = 0.f;
    }
    for (int idx = tid; idx < 3 * 36; idx += 128)
        v[49 + idx / 36][idx % 36] = 0.f;
    for (int idx = tid; idx < 3 * 53; idx += 128)
        sc[49 + idx / 53][idx % 53] = 0.f;
    if (shifted && tid < NTOK) {
        int wl = win & 63;
        int h = (wl >> 3) * WSZ + tid / WSZ;
        int w = (wl & 7)  * WSZ + tid % WSZ;
        int rc = (h < HH  - WSZ) ? 0 : ((h < HH  - SSHIFT) ? 1 : 2);
        int cc = (w < WW2 - WSZ) ? 0 : ((w < WW2 - SSHIFT) ? 1 : 2);
        lab[tid] = rc * 3 + cc;
    }
    __syncthreads();

    // ---- scores: 13x13 grid of 4x4 tiles ----
    for (int t = tid; t < 169; t += 128) {
        int ti = t % 13, tj = t / 13;
        int i0 = ti * 4, j0 = tj * 4;
        float a[4][4];
        #pragma unroll
        for (int r = 0; r < 4; r++)
            #pragma unroll
            for (int c = 0; c < 4; c++) a[r][c] = 0.f;
        #pragma unroll 8
        for (int d = 0; d < HDIM; d++) {
            float qr[4], kr[4];
            #pragma unroll
            for (int r = 0; r < 4; r++) qr[r] = q[i0 + r][d];
            #pragma unroll
            for (int c = 0; c < 4; c++) kr[c] = k[j0 + c][d];
            #pragma unroll
            for (int r = 0; r < 4; r++)
                #pragma unroll
                for (int c = 0; c < 4; c++)
                    a[r][c] = fmaf(qr[r], kr[c], a[r][c]);
        }
        #pragma unroll
        for (int r = 0; r < 4; r++) {
            int i = i0 + r;
            if (i >= NTOK) break;
            int li = shifted ? lab[i] : 0;
            #pragma unroll
            for (int c = 0; c < 4; c++) {
                int j = j0 + c;
                if (j < NTOK) {
                    int ridx = (i / WSZ - j / WSZ + WSZ - 1) * (2 * WSZ - 1)
                             + (i % WSZ - j % WSZ + WSZ - 1);
                    float val = a[r][c] + rpb[ridx * NHEADS + hd];
                    if (shifted && li != lab[j]) val -= 100.f;
                    sc[i][j] = val;
                }
            }
        }
    }
    __syncthreads();

    // ---- softmax rows ----
    int warp = tid >> 5, lane = tid & 31;
    for (int i = warp; i < NTOK; i += 4) {
        float a0 = (lane < NTOK)      ? sc[i][lane]      : -1e30f;
        float a1 = (lane + 32 < NTOK) ? sc[i][lane + 32] : -1e30f;
        float mx = fmaxf(a0, a1);
        #pragma unroll
        for (int o = 16; o > 0; o >>= 1) mx = fmaxf(mx, __shfl_xor_sync(0xffffffffu, mx, o));
        float e0 = (lane < NTOK)      ? __expf(a0 - mx) : 0.f;
        float e1 = (lane + 32 < NTOK) ? __expf(a1 - mx) : 0.f;
        float sum = e0 + e1;
        #pragma unroll
        for (int o = 16; o > 0; o >>= 1) sum += __shfl_xor_sync(0xffffffffu, sum, o);
        float inv = 1.f / sum;
        if (lane < NTOK)      sc[i][lane]      = e0 * inv;
        if (lane + 32 < NTOK) sc[i][lane + 32] = e1 * inv;
    }
    __syncthreads();

    // ---- AV: 13 i-blocks x 8 d-blocks of 4x4 ----
    if (tid < 104) {
        int i0 = (tid % 13) * 4, d0 = (tid / 13) * 4;
        float a2[4][4];
        #pragma unroll
        for (int r = 0; r < 4; r++)
            #pragma unroll
            for (int c = 0; c < 4; c++) a2[r][c] = 0.f;
        #pragma unroll 7
        for (int j = 0; j < NTOK; j++) {
            float4 vv = *(const float4*)&v[j][d0];
            float s0 = sc[i0 + 0][j], s1 = sc[i0 + 1][j];
            float s2 = sc[i0 + 2][j], s3 = sc[i0 + 3][j];
            a2[0][0] = fmaf(s0, vv.x, a2[0][0]); a2[0][1] = fmaf(s0, vv.y, a2[0][1]);
            a2[0][2] = fmaf(s0, vv.z, a2[0][2]); a2[0][3] = fmaf(s0, vv.w, a2[0][3]);
            a2[1][0] = fmaf(s1, vv.x, a2[1][0]); a2[1][1] = fmaf(s1, vv.y, a2[1][1]);
            a2[1][2] = fmaf(s1, vv.z, a2[1][2]); a2[1][3] = fmaf(s1, vv.w, a2[1][3]);
            a2[2][0] = fmaf(s2, vv.x, a2[2][0]); a2[2][1] = fmaf(s2, vv.y, a2[2][1]);
            a2[2][2] = fmaf(s2, vv.z, a2[2][2]); a2[2][3] = fmaf(s2, vv.w, a2[2][3]);
            a2[3][0] = fmaf(s3, vv.x, a2[3][0]); a2[3][1] = fmaf(s3, vv.y, a2[3][1]);
            a2[3][2] = fmaf(s3, vv.z, a2[3][2]); a2[3][3] = fmaf(s3, vv.w, a2[3][3]);
        }
        size_t ob = (size_t)win * NTOK * CC + hd * HDIM;
        #pragma unroll
        for (int r = 0; r < 4; r++) {
            int i = i0 + r;
            if (i < NTOK) {
                size_t o = ob + (size_t)i * CC + d0;
                #pragma unroll
                for (int c = 0; c < 4; c += 2) {
                    float vx = a2[r][c], vy = a2[r][c + 1];
                    __nv_bfloat16 hx = __float2bfloat16_rn(vx);
                    __nv_bfloat16 hy = __float2bfloat16_rn(vy);
                    __nv_bfloat162 hp; hp.x = hx; hp.y = hy;
                    __nv_bfloat162 lp;
                    lp.x = __float2bfloat16_rn(vx - __bfloat162float(hx));
                    lp.y = __float2bfloat16_rn(vy - __bfloat162float(hy));
                    *(__nv_bfloat162*)&oh[o + c] = hp;
                    *(__nv_bfloat162*)&ol[o + c] = lp;
                }
            }
        }
    }
}

// ====================== pure bf16 hi/lo GEMM, ldmatrix + BK=64, 2-stage ======================
// CTA 128x64, warp grid 4x2, warp tile 32x32, 3 passes: Ah*Bh + Al*Bh + Ah*Bl.
#define BKK     64
#define STRD    72                  // 64 + 8 pad -> 144B rows (conflict-free LDSM)
#define OFF_AH  0
#define OFF_AL  9216
#define OFF_BH  18432
#define OFF_BL  23040
#define STAGE   27648               // elems per stage
#define GSMEM   (2 * STAGE * 2)     // 110592 bytes

__device__ __forceinline__ void mma16816(float* c, const uint32_t* a, const uint32_t* b)
{
    asm volatile(
        "mma.sync.aligned.m16n8k16.row.col.f32.bf16.bf16.f32 "
        "{%0,%1,%2,%3}, {%4,%5,%6,%7}, {%8,%9}, {%0,%1,%2,%3};"
        : "+f"(c[0]), "+f"(c[1]), "+f"(c[2]), "+f"(c[3])
        : "r"(a[0]), "r"(a[1]), "r"(a[2]), "r"(a[3]), "r"(b[0]), "r"(b[1]));
}
__device__ __forceinline__ void ldsm_x4(uint32_t* r, uint32_t addr)
{
    asm volatile("ldmatrix.sync.aligned.m8n8.x4.shared.b16 {%0,%1,%2,%3}, [%4];"
        : "=r"(r[0]), "=r"(r[1]), "=r"(r[2]), "=r"(r[3]) : "r"(addr));
}
__device__ __forceinline__ void cp_async16(uint32_t smem, const void* gmem)
{
    asm volatile("cp.async.cg.shared.global [%0], [%1], 16;" :: "r"(smem), "l"(gmem));
}
#define CP_COMMIT()  asm volatile("cp.async.commit_group;")
#define CP_WAIT(n)   asm volatile("cp.async.wait_group %0;" :: "n"(n))

template<int EPI>
__global__ __launch_bounds__(256, 2) void gemm_bf16_kernel(
    const __nv_bfloat16* __restrict__ Ah, const __nv_bfloat16* __restrict__ Al,
    const __nv_bfloat16* __restrict__ Bh, const __nv_bfloat16* __restrict__ Bl,
    const float* __restrict__ bias, float* __restrict__ Cout,
    const float* __restrict__ resid,
    __nv_bfloat16* __restrict__ OutH, __nv_bfloat16* __restrict__ OutL,
    int N, int K, int shifted)
{
    extern __shared__ __nv_bfloat16 sm[];
    uint32_t smb = (uint32_t)__cvta_generic_to_shared(sm);
    int tid = threadIdx.x;
    int wid = tid >> 5, lane = tid & 31;
    int wr = wid >> 1, wc = wid & 1;          // 4x2 warp grid
    int g = lane >> 2, t2 = (lane & 3) * 2;
    int m0 = blockIdx.y * 128, n0 = blockIdx.x * 64;

    // cp.async loader mapping
    int arow = tid >> 1, aq = (tid & 1) * 4;        // A: 4 chunks per part
    int brow = tid >> 2, bq = (tid & 3) * 2;        // B: 2 chunks per part
    const __nv_bfloat16* gAh = Ah + (size_t)(m0 + arow) * K + aq * 8;
    const __nv_bfloat16* gAl = Al + (size_t)(m0 + arow) * K + aq * 8;
    const __nv_bfloat16* gBh = Bh + (size_t)(n0 + brow) * K + bq * 8;
    const __nv_bfloat16* gBl = Bl + (size_t)(n0 + brow) * K + bq * 8;
    uint32_t sAh = smb + 2 * (OFF_AH + arow * STRD + aq * 8);
    uint32_t sAl = smb + 2 * (OFF_AL + arow * STRD + aq * 8);
    uint32_t sBh = smb + 2 * (OFF_BH + brow * STRD + bq * 8);
    uint32_t sBl = smb + 2 * (OFF_BL + brow * STRD + bq * 8);

    auto issue = [&](int kt) {
        uint32_t so = 2u * (uint32_t)((kt & 1) * STAGE);
        int ko = kt * BKK;
        #pragma unroll
        for (int c = 0; c < 4; c++) {
            cp_async16(sAh + so + c * 16, gAh + ko + c * 8);
            cp_async16(sAl + so + c * 16, gAl + ko + c * 8);
        }
        #pragma unroll
        for (int c = 0; c < 2; c++) {
            cp_async16(sBh + so + c * 16, gBh + ko + c * 8);
            cp_async16(sBl + so + c * 16, gBl + ko + c * 8);
        }
        CP_COMMIT();
    };

    // ldmatrix lane-address components (element offsets)
    int a_r = wr * 32 + (lane & 15);
    int a_c = (lane >> 4) * 8;
    int b_r = wc * 32 + (lane & 7) + ((lane >> 4) << 3);
    int b_c = ((lane >> 3) & 1) * 8;

    float acc[2][4][4];
    #pragma unroll
    for (int mt = 0; mt < 2; mt++)
        #pragma unroll
        for (int nt = 0; nt < 4; nt++)
            #pragma unroll
            for (int r = 0; r < 4; r++) acc[mt][nt][r] = 0.f;

    int KT = K >> 6;
    issue(0);
    if (KT > 1) issue(1);

    for (int kt = 0; kt < KT; kt++) {
        if (kt + 1 < KT) { CP_WAIT(1); } else { CP_WAIT(0); }
        __syncthreads();
        uint32_t sb = smb + 2u * (uint32_t)((kt & 1) * STAGE);
        #pragma unroll
        for (int kk = 0; kk < BKK; kk += 16) {
            uint32_t Afh[2][4], Afl[2][4], Bfh[4][2], Bfl[4][2];
            #pragma unroll
            for (int mt = 0; mt < 2; mt++)
                ldsm_x4(Afh[mt], sb + 2 * (OFF_AH + (a_r + mt * 16) * STRD + kk + a_c));
            #pragma unroll
            for (int p = 0; p < 2; p++) {
                uint32_t r[4];
                ldsm_x4(r, sb + 2 * (OFF_BH + (b_r + p * 16) * STRD + kk + b_c));
                Bfh[2*p][0] = r[0]; Bfh[2*p][1] = r[1];
                Bfh[2*p+1][0] = r[2]; Bfh[2*p+1][1] = r[3];
            }
            #pragma unroll
            for (int mt = 0; mt < 2; mt++)
                #pragma unroll
                for (int nt = 0; nt < 4; nt++)
                    mma16816(acc[mt][nt], Afh[mt], Bfh[nt]);
            #pragma unroll
            for (int mt = 0; mt < 2; mt++)
                ldsm_x4(Afl[mt], sb + 2 * (OFF_AL + (a_r + mt * 16) * STRD + kk + a_c));
            #pragma unroll
            for (int mt = 0; mt < 2; mt++)
                #pragma unroll
                for (int nt = 0; nt < 4; nt++)
                    mma16816(acc[mt][nt], Afl[mt], Bfh[nt]);
            #pragma unroll
            for (int p = 0; p < 2; p++) {
                uint32_t r[4];
                ldsm_x4(r, sb + 2 * (OFF_BL + (b_r + p * 16) * STRD + kk + b_c));
                Bfl[2*p][0] = r[0]; Bfl[2*p][1] = r[1];
                Bfl[2*p+1][0] = r[2]; Bfl[2*p+1][1] = r[3];
            }
            #pragma unroll
            for (int mt = 0; mt < 2; mt++)
                #pragma unroll
                for (int nt = 0; nt < 4; nt++)
                    mma16816(acc[mt][nt], Afh[mt], Bfl[nt]);
        }
        __syncthreads();
        if (kt + 2 < KT) issue(kt + 2);
    }

    // ---- epilogue ----
    #pragma unroll
    for (int mt = 0; mt < 2; mt++) {
        #pragma unroll
        for (int hf = 0; hf < 2; hf++) {
            int m = m0 + wr * 32 + mt * 16 + hf * 8 + g;
            size_t orow;
            if (EPI == 1) {
                int win = m / NTOK, n = m - win * NTOK;
                int b = win >> 6, wl = win & 63;
                int hs = (wl >> 3) * WSZ + n / WSZ;
                int ws = (wl & 7)  * WSZ + n % WSZ;
                if (shifted) { hs = (hs + SSHIFT) % HH; ws = (ws + SSHIFT) % WW2; }
                orow = (((size_t)b * HH + hs) * WW2 + ws) * CC;
            } else if (EPI == 3) {
                orow = (size_t)m * CC;
            } else {
                orow = (size_t)m * N;
            }
            #pragma unroll
            for (int nt = 0; nt < 4; nt++) {
                int n = n0 + wc * 32 + nt * 8 + t2;
                float vx = acc[mt][nt][hf * 2 + 0] + bias[n];
                float vy = acc[mt][nt][hf * 2 + 1] + bias[n + 1];
                if (EPI == 2) {
                    vx = 0.5f * vx * (1.f + erff(vx * 0.70710678118654752f));
                    vy = 0.5f * vy * (1.f + erff(vy * 0.70710678118654752f));
                    __nv_bfloat16 hx = __float2bfloat16_rn(vx);
                    __nv_bfloat16 hy = __float2bfloat16_rn(vy);
                    __nv_bfloat162 hp; hp.x = hx; hp.y = hy;
                    __nv_bfloat162 lp;
                    lp.x = __float2bfloat16_rn(vx - __bfloat162float(hx));
                    lp.y = __float2bfloat16_rn(vy - __bfloat162float(hy));
                    *(__nv_bfloat162*)&OutH[orow + n] = hp;
                    *(__nv_bfloat162*)&OutL[orow + n] = lp;
                } else if (EPI == 0) {
                    float2 v = {vx, vy};
                    *(float2*)&Cout[orow + n] = v;
                } else {
                    float2 r = *(const float2*)&resid[orow + n];
                    float2 v = {r.x + vx, r.y + vy};
                    *(float2*)&Cout[orow + n] = v;
                }
            }
        }
    }
}

// ====================== launch ======================
extern "C" void kernel_launch(void* const* d_in, const int* in_sizes, int n_in,
                              void* d_out, int out_size)
{
    (void)in_sizes; (void)n_in; (void)out_size;
    const float* x     = (const float*)d_in[0];
    const float* ln1g  = (const float*)d_in[1];
    const float* ln1b  = (const float*)d_in[2];
    const float* qkvw  = (const float*)d_in[3];
    const float* qkvb  = (const float*)d_in[4];
    const float* rpb   = (const float*)d_in[5];
    const float* projw = (const float*)d_in[6];
    const float* projb = (const float*)d_in[7];
    const float* ln2g  = (const float*)d_in[8];
    const float* ln2b  = (const float*)d_in[9];
    const float* fc1w  = (const float*)d_in[10];
    const float* fc1b  = (const float*)d_in[11];
    const float* fc2w  = (const float*)d_in[12];
    const float* fc2b  = (const float*)d_in[13];
    float* out = (float*)d_out;

    float *X, *QKV;
    __nv_bfloat16 *Ah, *Al, *H1h, *H1l;
    cudaGetSymbolAddress((void**)&X,   g_X);
    cudaGetSymbolAddress((void**)&QKV, g_QKV);
    cudaGetSymbolAddress((void**)&Ah,  g_Ah);
    cudaGetSymbolAddress((void**)&Al,  g_Al);
    cudaGetSymbolAddress((void**)&H1h, g_H1h);
    cudaGetSymbolAddress((void**)&H1l, g_H1l);

    __nv_bfloat16 *Wqh, *Wql, *Wph, *Wpl, *W1h, *W1l, *W2h, *W2l;
    cudaGetSymbolAddress((void**)&Wqh, g_Wqkv_h); cudaGetSymbolAddress((void**)&Wql, g_Wqkv_l);
    cudaGetSymbolAddress((void**)&Wph, g_Wprj_h); cudaGetSymbolAddress((void**)&Wpl, g_Wprj_l);
    cudaGetSymbolAddress((void**)&W1h, g_Wfc1_h); cudaGetSymbolAddress((void**)&W1l, g_Wfc1_l);
    cudaGetSymbolAddress((void**)&W2h, g_Wfc2_h); cudaGetSymbolAddress((void**)&W2l, g_Wfc2_l);

    cudaFuncSetAttribute(gemm_bf16_kernel<0>, cudaFuncAttributeMaxDynamicSharedMemorySize, GSMEM);
    cudaFuncSetAttribute(gemm_bf16_kernel<1>, cudaFuncAttributeMaxDynamicSharedMemorySize, GSMEM);
    cudaFuncSetAttribute(gemm_bf16_kernel<2>, cudaFuncAttributeMaxDynamicSharedMemorySize, GSMEM);
    cudaFuncSetAttribute(gemm_bf16_kernel<3>, cudaFuncAttributeMaxDynamicSharedMemorySize, GSMEM);

    for (int layer = 0; layer < 2; layer++) {
        size_t oq = (size_t)layer * 192 * 576;
        size_t op = (size_t)layer * 192 * 192;
        size_t o1 = (size_t)layer * 192 * 768;
        size_t o2 = (size_t)layer * 768 * 192;
        wsplit_layer_kernel<<<1728, 256>>>(
            qkvw + oq, projw + op, fc1w + o1, fc2w + o2,
            Wqh + oq, Wql + oq, Wph + op, Wpl + op,
            W1h + o1, W1l + o1, W2h + o2, W2l + o2);
    }

    const int MB = TTOT / 128;  // 1568
    for (int layer = 0; layer < 2; layer++) {
        int shifted = layer & 1;
        size_t oq = (size_t)layer * 192 * 576;
        size_t op = (size_t)layer * 192 * 192;
        size_t o1 = (size_t)layer * 192 * 768;
        size_t o2 = (size_t)layer * 768 * 192;
        const float* pre = (layer == 0) ? x : X;
        float* fc2_out   = (layer == 0) ? X : out;

        lnsplit_kernel<<<TTOT / 8, 256>>>(pre, Ah, Al,
            ln1g + layer * CC, ln1b + layer * CC, 1, shifted);
        gemm_bf16_kernel<0><<<dim3(9, MB), 256, GSMEM>>>(
            Ah, Al, Wqh + oq, Wql + oq, qkvb + layer * 576, QKV,
            nullptr, nullptr, nullptr, 576, 192, 0);
        attn_kernel<<<NWINS * NHEADS, 128>>>(QKV, Ah, Al, rpb + layer * 169 * NHEADS, shifted);
        gemm_bf16_kernel<1><<<dim3(3, MB), 256, GSMEM>>>(
            Ah, Al, Wph + op, Wpl + op, projb + layer * CC, X,
            pre, nullptr, nullptr, 192, 192, shifted);
        lnsplit_kernel<<<TTOT / 8, 256>>>(X, Ah, Al,
            ln2g + layer * CC, ln2b + layer * CC, 0, 0);
        gemm_bf16_kernel<2><<<dim3(12, MB), 256, GSMEM>>>(
            Ah, Al, W1h + o1, W1l + o1, fc1b + layer * HIDDIM, nullptr,
            nullptr, H1h, H1l, 768, 192, 0);
        gemm_bf16_kernel<3><<<dim3(3, MB), 256, GSMEM>>>(
            H1h, H1l, W2h + o2, W2l + o2, fc2b + layer * CC, fc2_out,
            X, nullptr, nullptr, 192, 768, 0);
    }
}

// round 11
// speedup vs baseline: 1.8244x; 1.0870x over previous
#include <cuda_runtime.h>
#include <cuda_bf16.h>
#include <math.h>
#include <cstdint>

// ---------------- problem constants ----------------
#define HH      56
#define WW2     56
#define CC      192
#define NHEADS  6
#define WSZ     7
#define SSHIFT  3
#define HIDDIM  768
#define NTOK    49
#define HDIM    32
#define NWINS   4096
#define TTOT    200704
#define SCALEQ  0.17677669529663687f

// ---------------- scratch ----------------
__device__ float g_X  [(size_t)TTOT * CC];          // residual stream fp32
__device__ float g_QKV[(size_t)TTOT * 3 * CC];      // qkv fp32 (window order)
__device__ __nv_bfloat16 g_Ah [(size_t)TTOT * CC];      // activation hi (GEMM A)
__device__ __nv_bfloat16 g_Al [(size_t)TTOT * CC];      // activation lo
__device__ __nv_bfloat16 g_H1h[(size_t)TTOT * HIDDIM];  // MLP hidden hi
__device__ __nv_bfloat16 g_H1l[(size_t)TTOT * HIDDIM];  // MLP hidden lo

// split weights, transposed to [N][K] bf16 (hi + lo)
__device__ __nv_bfloat16 g_Wqkv_h[2 * 576 * 192];
__device__ __nv_bfloat16 g_Wqkv_l[2 * 576 * 192];
__device__ __nv_bfloat16 g_Wprj_h[2 * 192 * 192];
__device__ __nv_bfloat16 g_Wprj_l[2 * 192 * 192];
__device__ __nv_bfloat16 g_Wfc1_h[2 * 768 * 192];
__device__ __nv_bfloat16 g_Wfc1_l[2 * 768 * 192];
__device__ __nv_bfloat16 g_Wfc2_h[2 * 192 * 768];
__device__ __nv_bfloat16 g_Wfc2_l[2 * 192 * 768];

// ====================== weight transpose + split (one layer) ======================
__global__ __launch_bounds__(256) void wsplit_layer_kernel(
    const float* __restrict__ qkvw, const float* __restrict__ projw,
    const float* __restrict__ fc1w, const float* __restrict__ fc2w,
    __nv_bfloat16* __restrict__ qh, __nv_bfloat16* __restrict__ ql,
    __nv_bfloat16* __restrict__ ph, __nv_bfloat16* __restrict__ pl,
    __nv_bfloat16* __restrict__ f1h, __nv_bfloat16* __restrict__ f1l,
    __nv_bfloat16* __restrict__ f2h, __nv_bfloat16* __restrict__ f2l)
{
    int idx = blockIdx.x * 256 + threadIdx.x;
    const float* W; __nv_bfloat16 *Hp, *Lp; int K, N, off;
    if (idx < 110592)       { W = qkvw; Hp = qh;  Lp = ql;  K = 192; N = 576; off = idx; }
    else if (idx < 147456)  { W = projw; Hp = ph; Lp = pl;  K = 192; N = 192; off = idx - 110592; }
    else if (idx < 294912)  { W = fc1w; Hp = f1h; Lp = f1l; K = 192; N = 768; off = idx - 147456; }
    else if (idx < 442368)  { W = fc2w; Hp = f2h; Lp = f2l; K = 768; N = 192; off = idx - 294912; }
    else return;
    int k = off / N, n = off - k * N;
    float v = W[off];
    __nv_bfloat16 h = __float2bfloat16_rn(v);
    __nv_bfloat16 l = __float2bfloat16_rn(v - __bfloat162float(h));
    Hp[(size_t)n * K + k] = h;
    Lp[(size_t)n * K + k] = l;
}

// ====================== LN + (optional window gather) + hi/lo split ======================
__global__ __launch_bounds__(256) void lnsplit_kernel(
    const float* __restrict__ src,
    __nv_bfloat16* __restrict__ oh, __nv_bfloat16* __restrict__ ol,
    const float* __restrict__ g, const float* __restrict__ bta,
    int gather, int shifted)
{
    int warp = threadIdx.x >> 5, lane = threadIdx.x & 31;
    int m = blockIdx.x * 8 + warp;
    size_t tok;
    if (gather) {
        int win = m / NTOK, n = m - win * NTOK;
        int b = win >> 6, wl = win & 63;
        int hs = (wl >> 3) * WSZ + n / WSZ;
        int ws = (wl & 7)  * WSZ + n % WSZ;
        if (shifted) { hs = (hs + SSHIFT) % HH; ws = (ws + SSHIFT) % WW2; }
        tok = ((size_t)b * HH + hs) * WW2 + ws;
    } else {
        tok = (size_t)m;
    }
    const float* xp = src + tok * CC;
    float v[6]; float s = 0.f, ss = 0.f;
    #pragma unroll
    for (int j = 0; j < 6; j++) { v[j] = xp[lane + 32*j]; s += v[j]; ss += v[j]*v[j]; }
    #pragma unroll
    for (int o = 16; o > 0; o >>= 1) {
        s  += __shfl_xor_sync(0xffffffffu, s,  o);
        ss += __shfl_xor_sync(0xffffffffu, ss, o);
    }
    float mu = s * (1.f / CC);
    float rstd = rsqrtf(ss * (1.f / CC) - mu * mu + 1e-5f);
    __nv_bfloat16* ophi = oh + (size_t)m * CC;
    __nv_bfloat16* oplo = ol + (size_t)m * CC;
    #pragma unroll
    for (int j = 0; j < 6; j++) {
        int c = lane + 32*j;
        float f = (v[j] - mu) * rstd * g[c] + bta[c];
        __nv_bfloat16 h = __float2bfloat16_rn(f);
        ophi[c] = h;
        oplo[c] = __float2bfloat16_rn(f - __bfloat162float(h));
    }
}

// ====================== window attention (register-blocked) ======================
__global__ __launch_bounds__(128) void attn_kernel(
    const float* __restrict__ qkv,
    __nv_bfloat16* __restrict__ oh, __nv_bfloat16* __restrict__ ol,
    const float* __restrict__ rpb, int shifted)
{
    int win = blockIdx.x / NHEADS;
    int hd  = blockIdx.x % NHEADS;
    __shared__ __align__(16) float q[52][33];
    __shared__ __align__(16) float k[52][33];
    __shared__ __align__(16) float v[52][36];
    __shared__ __align__(16) float sc[52][53];
    __shared__ int lab[52];
    int tid = threadIdx.x;

    const float* base = qkv + (size_t)win * NTOK * 576 + hd * HDIM;
    for (int idx = tid; idx < NTOK * HDIM; idx += 128) {
        int i = idx >> 5, d = idx & 31;
        const float* row = base + (size_t)i * 576 + d;
        q[i][d] = row[0]   * SCALEQ;
        k[i][d] = row[192];
        v[i][d] = row[384];
    }
    for (int idx = tid; idx < 3 * 33; idx += 128) {
        q[49 + idx / 33][idx % 33] = 0.f;
        k[49 + idx / 33][idx % 33] = 0.f;
    }
    for (int idx = tid; idx < 3 * 36; idx += 128)
        v[49 + idx / 36][idx % 36] = 0.f;
    for (int idx = tid; idx < 3 * 53; idx += 128)
        sc[49 + idx / 53][idx % 53] = 0.f;
    if (shifted && tid < NTOK) {
        int wl = win & 63;
        int h = (wl >> 3) * WSZ + tid / WSZ;
        int w = (wl & 7)  * WSZ + tid % WSZ;
        int rc = (h < HH  - WSZ) ? 0 : ((h < HH  - SSHIFT) ? 1 : 2);
        int cc = (w < WW2 - WSZ) ? 0 : ((w < WW2 - SSHIFT) ? 1 : 2);
        lab[tid] = rc * 3 + cc;
    }
    __syncthreads();

    for (int t = tid; t < 169; t += 128) {
        int ti = t % 13, tj = t / 13;
        int i0 = ti * 4, j0 = tj * 4;
        float a[4][4];
        #pragma unroll
        for (int r = 0; r < 4; r++)
            #pragma unroll
            for (int c = 0; c < 4; c++) a[r][c] = 0.f;
        #pragma unroll 8
        for (int d = 0; d < HDIM; d++) {
            float qr[4], kr[4];
            #pragma unroll
            for (int r = 0; r < 4; r++) qr[r] = q[i0 + r][d];
            #pragma unroll
            for (int c = 0; c < 4; c++) kr[c] = k[j0 + c][d];
            #pragma unroll
            for (int r = 0; r < 4; r++)
                #pragma unroll
                for (int c = 0; c < 4; c++)
                    a[r][c] = fmaf(qr[r], kr[c], a[r][c]);
        }
        #pragma unroll
        for (int r = 0; r < 4; r++) {
            int i = i0 + r;
            if (i >= NTOK) break;
            int li = shifted ? lab[i] : 0;
            #pragma unroll
            for (int c = 0; c < 4; c++) {
                int j = j0 + c;
                if (j < NTOK) {
                    int ridx = (i / WSZ - j / WSZ + WSZ - 1) * (2 * WSZ - 1)
                             + (i % WSZ - j % WSZ + WSZ - 1);
                    float val = a[r][c] + rpb[ridx * NHEADS + hd];
                    if (shifted && li != lab[j]) val -= 100.f;
                    sc[i][j] = val;
                }
            }
        }
    }
    __syncthreads();

    int warp = tid >> 5, lane = tid & 31;
    for (int i = warp; i < NTOK; i += 4) {
        float a0 = (lane < NTOK)      ? sc[i][lane]      : -1e30f;
        float a1 = (lane + 32 < NTOK) ? sc[i][lane + 32] : -1e30f;
        float mx = fmaxf(a0, a1);
        #pragma unroll
        for (int o = 16; o > 0; o >>= 1) mx = fmaxf(mx, __shfl_xor_sync(0xffffffffu, mx, o));
        float e0 = (lane < NTOK)      ? __expf(a0 - mx) : 0.f;
        float e1 = (lane + 32 < NTOK) ? __expf(a1 - mx) : 0.f;
        float sum = e0 + e1;
        #pragma unroll
        for (int o = 16; o > 0; o >>= 1) sum += __shfl_xor_sync(0xffffffffu, sum, o);
        float inv = 1.f / sum;
        if (lane < NTOK)      sc[i][lane]      = e0 * inv;
        if (lane + 32 < NTOK) sc[i][lane + 32] = e1 * inv;
    }
    __syncthreads();

    if (tid < 104) {
        int i0 = (tid % 13) * 4, d0 = (tid / 13) * 4;
        float a2[4][4];
        #pragma unroll
        for (int r = 0; r < 4; r++)
            #pragma unroll
            for (int c = 0; c < 4; c++) a2[r][c] = 0.f;
        #pragma unroll 7
        for (int j = 0; j < NTOK; j++) {
            float4 vv = *(const float4*)&v[j][d0];
            float s0 = sc[i0 + 0][j], s1 = sc[i0 + 1][j];
            float s2 = sc[i0 + 2][j], s3 = sc[i0 + 3][j];
            a2[0][0] = fmaf(s0, vv.x, a2[0][0]); a2[0][1] = fmaf(s0, vv.y, a2[0][1]);
            a2[0][2] = fmaf(s0, vv.z, a2[0][2]); a2[0][3] = fmaf(s0, vv.w, a2[0][3]);
            a2[1][0] = fmaf(s1, vv.x, a2[1][0]); a2[1][1] = fmaf(s1, vv.y, a2[1][1]);
            a2[1][2] = fmaf(s1, vv.z, a2[1][2]); a2[1][3] = fmaf(s1, vv.w, a2[1][3]);
            a2[2][0] = fmaf(s2, vv.x, a2[2][0]); a2[2][1] = fmaf(s2, vv.y, a2[2][1]);
            a2[2][2] = fmaf(s2, vv.z, a2[2][2]); a2[2][3] = fmaf(s2, vv.w, a2[2][3]);
            a2[3][0] = fmaf(s3, vv.x, a2[3][0]); a2[3][1] = fmaf(s3, vv.y, a2[3][1]);
            a2[3][2] = fmaf(s3, vv.z, a2[3][2]); a2[3][3] = fmaf(s3, vv.w, a2[3][3]);
        }
        size_t ob = (size_t)win * NTOK * CC + hd * HDIM;
        #pragma unroll
        for (int r = 0; r < 4; r++) {
            int i = i0 + r;
            if (i < NTOK) {
                size_t o = ob + (size_t)i * CC + d0;
                #pragma unroll
                for (int c = 0; c < 4; c += 2) {
                    float vx = a2[r][c], vy = a2[r][c + 1];
                    __nv_bfloat16 hx = __float2bfloat16_rn(vx);
                    __nv_bfloat16 hy = __float2bfloat16_rn(vy);
                    __nv_bfloat162 hp; hp.x = hx; hp.y = hy;
                    __nv_bfloat162 lp;
                    lp.x = __float2bfloat16_rn(vx - __bfloat162float(hx));
                    lp.y = __float2bfloat16_rn(vy - __bfloat162float(hy));
                    *(__nv_bfloat162*)&oh[o + c] = hp;
                    *(__nv_bfloat162*)&ol[o + c] = lp;
                }
            }
        }
    }
}

// ====================== bf16 hi/lo GEMM: BK=32, 2-stage, 3 CTAs/SM ======================
// CTA 128x64, warp grid 4x2, warp tile 32x32, ldmatrix, 3 passes.
#define BKK     32
#define STRD    40                  // 32 + 8 pad -> 80B rows (conflict-free LDSM)
#define OFF_AH  0
#define OFF_AL  5120
#define OFF_BH  10240
#define OFF_BL  12800
#define STAGE   15360               // elems per stage
#define GSMEM   (2 * STAGE * 2)     // 61440 bytes

__device__ __forceinline__ void mma16816(float* c, const uint32_t* a, const uint32_t* b)
{
    asm volatile(
        "mma.sync.aligned.m16n8k16.row.col.f32.bf16.bf16.f32 "
        "{%0,%1,%2,%3}, {%4,%5,%6,%7}, {%8,%9}, {%0,%1,%2,%3};"
        : "+f"(c[0]), "+f"(c[1]), "+f"(c[2]), "+f"(c[3])
        : "r"(a[0]), "r"(a[1]), "r"(a[2]), "r"(a[3]), "r"(b[0]), "r"(b[1]));
}
__device__ __forceinline__ void ldsm_x4(uint32_t* r, uint32_t addr)
{
    asm volatile("ldmatrix.sync.aligned.m8n8.x4.shared.b16 {%0,%1,%2,%3}, [%4];"
        : "=r"(r[0]), "=r"(r[1]), "=r"(r[2]), "=r"(r[3]) : "r"(addr));
}
__device__ __forceinline__ void cp_async16(uint32_t smem, const void* gmem)
{
    asm volatile("cp.async.cg.shared.global [%0], [%1], 16;" :: "r"(smem), "l"(gmem));
}
#define CP_COMMIT()  asm volatile("cp.async.commit_group;")
#define CP_WAIT(n)   asm volatile("cp.async.wait_group %0;" :: "n"(n))

template<int EPI>
__global__ __launch_bounds__(256, 3) void gemm_bf16_kernel(
    const __nv_bfloat16* __restrict__ Ah, const __nv_bfloat16* __restrict__ Al,
    const __nv_bfloat16* __restrict__ Bh, const __nv_bfloat16* __restrict__ Bl,
    const float* __restrict__ bias, float* __restrict__ Cout,
    const float* __restrict__ resid,
    __nv_bfloat16* __restrict__ OutH, __nv_bfloat16* __restrict__ OutL,
    int N, int K, int shifted)
{
    extern __shared__ __nv_bfloat16 sm[];
    uint32_t smb = (uint32_t)__cvta_generic_to_shared(sm);
    int tid = threadIdx.x;
    int wid = tid >> 5, lane = tid & 31;
    int wr = wid >> 1, wc = wid & 1;          // 4x2 warp grid
    int g = lane >> 2, t2 = (lane & 3) * 2;
    int m0 = blockIdx.y * 128, n0 = blockIdx.x * 64;

    // cp.async loader mapping (BK=32)
    int arow = tid >> 1, aq = (tid & 1) * 2;        // A: 2 chunks per part
    int brow = tid >> 2, bq = tid & 3;              // B: 1 chunk per part
    const __nv_bfloat16* gAh = Ah + (size_t)(m0 + arow) * K + aq * 8;
    const __nv_bfloat16* gAl = Al + (size_t)(m0 + arow) * K + aq * 8;
    const __nv_bfloat16* gBh = Bh + (size_t)(n0 + brow) * K + bq * 8;
    const __nv_bfloat16* gBl = Bl + (size_t)(n0 + brow) * K + bq * 8;
    uint32_t sAh = smb + 2 * (OFF_AH + arow * STRD + aq * 8);
    uint32_t sAl = smb + 2 * (OFF_AL + arow * STRD + aq * 8);
    uint32_t sBh = smb + 2 * (OFF_BH + brow * STRD + bq * 8);
    uint32_t sBl = smb + 2 * (OFF_BL + brow * STRD + bq * 8);

    auto issue = [&](int kt) {
        uint32_t so = 2u * (uint32_t)((kt & 1) * STAGE);
        int ko = kt * BKK;
        cp_async16(sAh + so,      gAh + ko);
        cp_async16(sAh + so + 16, gAh + ko + 8);
        cp_async16(sAl + so,      gAl + ko);
        cp_async16(sAl + so + 16, gAl + ko + 8);
        cp_async16(sBh + so,      gBh + ko);
        cp_async16(sBl + so,      gBl + ko);
        CP_COMMIT();
    };

    // ldmatrix lane-address components (element offsets)
    int a_r = wr * 32 + (lane & 15);
    int a_c = (lane >> 4) * 8;
    int b_r = wc * 32 + (lane & 7) + ((lane >> 4) << 3);
    int b_c = ((lane >> 3) & 1) * 8;

    float acc[2][4][4];
    #pragma unroll
    for (int mt = 0; mt < 2; mt++)
        #pragma unroll
        for (int nt = 0; nt < 4; nt++)
            #pragma unroll
            for (int r = 0; r < 4; r++) acc[mt][nt][r] = 0.f;

    int KT = K >> 5;
    issue(0);
    if (KT > 1) issue(1);

    for (int kt = 0; kt < KT; kt++) {
        if (kt + 1 < KT) { CP_WAIT(1); } else { CP_WAIT(0); }
        __syncthreads();
        uint32_t sb = smb + 2u * (uint32_t)((kt & 1) * STAGE);
        #pragma unroll
        for (int kk = 0; kk < BKK; kk += 16) {
            uint32_t Afh[2][4], Afl[2][4], Bfh[4][2], Bfl[4][2];
            #pragma unroll
            for (int mt = 0; mt < 2; mt++)
                ldsm_x4(Afh[mt], sb + 2 * (OFF_AH + (a_r + mt * 16) * STRD + kk + a_c));
            #pragma unroll
            for (int p = 0; p < 2; p++) {
                uint32_t r[4];
                ldsm_x4(r, sb + 2 * (OFF_BH + (b_r + p * 16) * STRD + kk + b_c));
                Bfh[2*p][0] = r[0]; Bfh[2*p][1] = r[1];
                Bfh[2*p+1][0] = r[2]; Bfh[2*p+1][1] = r[3];
            }
            #pragma unroll
            for (int mt = 0; mt < 2; mt++)
                #pragma unroll
                for (int nt = 0; nt < 4; nt++)
                    mma16816(acc[mt][nt], Afh[mt], Bfh[nt]);
            #pragma unroll
            for (int mt = 0; mt < 2; mt++)
                ldsm_x4(Afl[mt], sb + 2 * (OFF_AL + (a_r + mt * 16) * STRD + kk + a_c));
            #pragma unroll
            for (int mt = 0; mt < 2; mt++)
                #pragma unroll
                for (int nt = 0; nt < 4; nt++)
                    mma16816(acc[mt][nt], Afl[mt], Bfh[nt]);
            #pragma unroll
            for (int p = 0; p < 2; p++) {
                uint32_t r[4];
                ldsm_x4(r, sb + 2 * (OFF_BL + (b_r + p * 16) * STRD + kk + b_c));
                Bfl[2*p][0] = r[0]; Bfl[2*p][1] = r[1];
                Bfl[2*p+1][0] = r[2]; Bfl[2*p+1][1] = r[3];
            }
            #pragma unroll
            for (int mt = 0; mt < 2; mt++)
                #pragma unroll
                for (int nt = 0; nt < 4; nt++)
                    mma16816(acc[mt][nt], Afh[mt], Bfl[nt]);
        }
        __syncthreads();
        if (kt + 2 < KT) issue(kt + 2);
    }

    // ---- epilogue ----
    #pragma unroll
    for (int mt = 0; mt < 2; mt++) {
        #pragma unroll
        for (int hf = 0; hf < 2; hf++) {
            int m = m0 + wr * 32 + mt * 16 + hf * 8 + g;
            size_t orow;
            if (EPI == 1) {
                int win = m / NTOK, n = m - win * NTOK;
                int b = win >> 6, wl = win & 63;
                int hs = (wl >> 3) * WSZ + n / WSZ;
                int ws = (wl & 7)  * WSZ + n % WSZ;
                if (shifted) { hs = (hs + SSHIFT) % HH; ws = (ws + SSHIFT) % WW2; }
                orow = (((size_t)b * HH + hs) * WW2 + ws) * CC;
            } else if (EPI == 3) {
                orow = (size_t)m * CC;
            } else {
                orow = (size_t)m * N;
            }
            #pragma unroll
            for (int nt = 0; nt < 4; nt++) {
                int n = n0 + wc * 32 + nt * 8 + t2;
                float vx = acc[mt][nt][hf * 2 + 0] + bias[n];
                float vy = acc[mt][nt][hf * 2 + 1] + bias[n + 1];
                if (EPI == 2) {
                    vx = 0.5f * vx * (1.f + erff(vx * 0.70710678118654752f));
                    vy = 0.5f * vy * (1.f + erff(vy * 0.70710678118654752f));
                    __nv_bfloat16 hx = __float2bfloat16_rn(vx);
                    __nv_bfloat16 hy = __float2bfloat16_rn(vy);
                    __nv_bfloat162 hp; hp.x = hx; hp.y = hy;
                    __nv_bfloat162 lp;
                    lp.x = __float2bfloat16_rn(vx - __bfloat162float(hx));
                    lp.y = __float2bfloat16_rn(vy - __bfloat162float(hy));
                    *(__nv_bfloat162*)&OutH[orow + n] = hp;
                    *(__nv_bfloat162*)&OutL[orow + n] = lp;
                } else if (EPI == 0) {
                    float2 v = {vx, vy};
                    *(float2*)&Cout[orow + n] = v;
                } else {
                    float2 r = *(const float2*)&resid[orow + n];
                    float2 v = {r.x + vx, r.y + vy};
                    *(float2*)&Cout[orow + n] = v;
                }
            }
        }
    }
}

// ====================== launch ======================
extern "C" void kernel_launch(void* const* d_in, const int* in_sizes, int n_in,
                              void* d_out, int out_size)
{
    (void)in_sizes; (void)n_in; (void)out_size;
    const float* x     = (const float*)d_in[0];
    const float* ln1g  = (const float*)d_in[1];
    const float* ln1b  = (const float*)d_in[2];
    const float* qkvw  = (const float*)d_in[3];
    const float* qkvb  = (const float*)d_in[4];
    const float* rpb   = (const float*)d_in[5];
    const float* projw = (const float*)d_in[6];
    const float* projb = (const float*)d_in[7];
    const float* ln2g  = (const float*)d_in[8];
    const float* ln2b  = (const float*)d_in[9];
    const float* fc1w  = (const float*)d_in[10];
    const float* fc1b  = (const float*)d_in[11];
    const float* fc2w  = (const float*)d_in[12];
    const float* fc2b  = (const float*)d_in[13];
    float* out = (float*)d_out;

    float *X, *QKV;
    __nv_bfloat16 *Ah, *Al, *H1h, *H1l;
    cudaGetSymbolAddress((void**)&X,   g_X);
    cudaGetSymbolAddress((void**)&QKV, g_QKV);
    cudaGetSymbolAddress((void**)&Ah,  g_Ah);
    cudaGetSymbolAddress((void**)&Al,  g_Al);
    cudaGetSymbolAddress((void**)&H1h, g_H1h);
    cudaGetSymbolAddress((void**)&H1l, g_H1l);

    __nv_bfloat16 *Wqh, *Wql, *Wph, *Wpl, *W1h, *W1l, *W2h, *W2l;
    cudaGetSymbolAddress((void**)&Wqh, g_Wqkv_h); cudaGetSymbolAddress((void**)&Wql, g_Wqkv_l);
    cudaGetSymbolAddress((void**)&Wph, g_Wprj_h); cudaGetSymbolAddress((void**)&Wpl, g_Wprj_l);
    cudaGetSymbolAddress((void**)&W1h, g_Wfc1_h); cudaGetSymbolAddress((void**)&W1l, g_Wfc1_l);
    cudaGetSymbolAddress((void**)&W2h, g_Wfc2_h); cudaGetSymbolAddress((void**)&W2l, g_Wfc2_l);

    cudaFuncSetAttribute(gemm_bf16_kernel<0>, cudaFuncAttributeMaxDynamicSharedMemorySize, GSMEM);
    cudaFuncSetAttribute(gemm_bf16_kernel<1>, cudaFuncAttributeMaxDynamicSharedMemorySize, GSMEM);
    cudaFuncSetAttribute(gemm_bf16_kernel<2>, cudaFuncAttributeMaxDynamicSharedMemorySize, GSMEM);
    cudaFuncSetAttribute(gemm_bf16_kernel<3>, cudaFuncAttributeMaxDynamicSharedMemorySize, GSMEM);

    for (int layer = 0; layer < 2; layer++) {
        size_t oq = (size_t)layer * 192 * 576;
        size_t op = (size_t)layer * 192 * 192;
        size_t o1 = (size_t)layer * 192 * 768;
        size_t o2 = (size_t)layer * 768 * 192;
        wsplit_layer_kernel<<<1728, 256>>>(
            qkvw + oq, projw + op, fc1w + o1, fc2w + o2,
            Wqh + oq, Wql + oq, Wph + op, Wpl + op,
            W1h + o1, W1l + o1, W2h + o2, W2l + o2);
    }

    const int MB = TTOT / 128;  // 1568
    for (int layer = 0; layer < 2; layer++) {
        int shifted = layer & 1;
        size_t oq = (size_t)layer * 192 * 576;
        size_t op = (size_t)layer * 192 * 192;
        size_t o1 = (size_t)layer * 192 * 768;
        size_t o2 = (size_t)layer * 768 * 192;
        const float* pre = (layer == 0) ? x : X;
        float* fc2_out   = (layer == 0) ? X : out;

        lnsplit_kernel<<<TTOT / 8, 256>>>(pre, Ah, Al,
            ln1g + layer * CC, ln1b + layer * CC, 1, shifted);
        gemm_bf16_kernel<0><<<dim3(9, MB), 256, GSMEM>>>(
            Ah, Al, Wqh + oq, Wql + oq, qkvb + layer * 576, QKV,
            nullptr, nullptr, nullptr, 576, 192, 0);
        attn_kernel<<<NWINS * NHEADS, 128>>>(QKV, Ah, Al, rpb + layer * 169 * NHEADS, shifted);
        gemm_bf16_kernel<1><<<dim3(3, MB), 256, GSMEM>>>(
            Ah, Al, Wph + op, Wpl + op, projb + layer * CC, X,
            pre, nullptr, nullptr, 192, 192, shifted);
        lnsplit_kernel<<<TTOT / 8, 256>>>(X, Ah, Al,
            ln2g + layer * CC, ln2b + layer * CC, 0, 0);
        gemm_bf16_kernel<2><<<dim3(12, MB), 256, GSMEM>>>(
            Ah, Al, W1h + o1, W1l + o1, fc1b + layer * HIDDIM, nullptr,
            nullptr, H1h, H1l, 768, 192, 0);
        gemm_bf16_kernel<3><<<dim3(3, MB), 256, GSMEM>>>(
            H1h, H1l, W2h + o2, W2l + o2, fc2b + layer * CC, fc2_out,
            X, nullptr, nullptr, 192, 768, 0);
    }
}

// round 12
// speedup vs baseline: 1.8274x; 1.0016x over previous
#include <cuda_runtime.h>
#include <cuda_bf16.h>
#include <math.h>
#include <cstdint>

// ---------------- problem constants ----------------
#define HH      56
#define WW2     56
#define CC      192
#define NHEADS  6
#define WSZ     7
#define SSHIFT  3
#define HIDDIM  768
#define NTOK    49
#define HDIM    32
#define NWINS   4096
#define TTOT    200704
#define SCALEQ  0.17677669529663687f

// ---------------- scratch ----------------
__device__ float g_X  [(size_t)TTOT * CC];          // residual stream fp32
__device__ float g_QKV[(size_t)TTOT * 3 * CC];      // qkv fp32 (window order)
__device__ __nv_bfloat16 g_Ah [(size_t)TTOT * CC];      // activation hi (GEMM A)
__device__ __nv_bfloat16 g_Al [(size_t)TTOT * CC];      // activation lo
__device__ __nv_bfloat16 g_H1h[(size_t)TTOT * HIDDIM];  // MLP hidden hi
__device__ __nv_bfloat16 g_H1l[(size_t)TTOT * HIDDIM];  // MLP hidden lo

// split weights, transposed to [N][K] bf16 (hi + lo)
__device__ __nv_bfloat16 g_Wqkv_h[2 * 576 * 192];
__device__ __nv_bfloat16 g_Wqkv_l[2 * 576 * 192];
__device__ __nv_bfloat16 g_Wprj_h[2 * 192 * 192];
__device__ __nv_bfloat16 g_Wprj_l[2 * 192 * 192];
__device__ __nv_bfloat16 g_Wfc1_h[2 * 768 * 192];
__device__ __nv_bfloat16 g_Wfc1_l[2 * 768 * 192];
__device__ __nv_bfloat16 g_Wfc2_h[2 * 192 * 768];
__device__ __nv_bfloat16 g_Wfc2_l[2 * 192 * 768];

// ====================== weight transpose + split (one layer) ======================
__global__ __launch_bounds__(256) void wsplit_layer_kernel(
    const float* __restrict__ qkvw, const float* __restrict__ projw,
    const float* __restrict__ fc1w, const float* __restrict__ fc2w,
    __nv_bfloat16* __restrict__ qh, __nv_bfloat16* __restrict__ ql,
    __nv_bfloat16* __restrict__ ph, __nv_bfloat16* __restrict__ pl,
    __nv_bfloat16* __restrict__ f1h, __nv_bfloat16* __restrict__ f1l,
    __nv_bfloat16* __restrict__ f2h, __nv_bfloat16* __restrict__ f2l)
{
    int idx = blockIdx.x * 256 + threadIdx.x;
    const float* W; __nv_bfloat16 *Hp, *Lp; int K, N, off;
    if (idx < 110592)       { W = qkvw; Hp = qh;  Lp = ql;  K = 192; N = 576; off = idx; }
    else if (idx < 147456)  { W = projw; Hp = ph; Lp = pl;  K = 192; N = 192; off = idx - 110592; }
    else if (idx < 294912)  { W = fc1w; Hp = f1h; Lp = f1l; K = 192; N = 768; off = idx - 147456; }
    else if (idx < 442368)  { W = fc2w; Hp = f2h; Lp = f2l; K = 768; N = 192; off = idx - 294912; }
    else return;
    int k = off / N, n = off - k * N;
    float v = W[off];
    __nv_bfloat16 h = __float2bfloat16_rn(v);
    __nv_bfloat16 l = __float2bfloat16_rn(v - __bfloat162float(h));
    Hp[(size_t)n * K + k] = h;
    Lp[(size_t)n * K + k] = l;
}

// ====================== LN + (optional window gather) + hi/lo split ======================
__global__ __launch_bounds__(256) void lnsplit_kernel(
    const float* __restrict__ src,
    __nv_bfloat16* __restrict__ oh, __nv_bfloat16* __restrict__ ol,
    const float* __restrict__ g, const float* __restrict__ bta,
    int gather, int shifted)
{
    int warp = threadIdx.x >> 5, lane = threadIdx.x & 31;
    int m = blockIdx.x * 8 + warp;
    size_t tok;
    if (gather) {
        int win = m / NTOK, n = m - win * NTOK;
        int b = win >> 6, wl = win & 63;
        int hs = (wl >> 3) * WSZ + n / WSZ;
        int ws = (wl & 7)  * WSZ + n % WSZ;
        if (shifted) { hs = (hs + SSHIFT) % HH; ws = (ws + SSHIFT) % WW2; }
        tok = ((size_t)b * HH + hs) * WW2 + ws;
    } else {
        tok = (size_t)m;
    }
    const float* xp = src + tok * CC;
    float v[6]; float s = 0.f, ss = 0.f;
    #pragma unroll
    for (int j = 0; j < 6; j++) { v[j] = xp[lane + 32*j]; s += v[j]; ss += v[j]*v[j]; }
    #pragma unroll
    for (int o = 16; o > 0; o >>= 1) {
        s  += __shfl_xor_sync(0xffffffffu, s,  o);
        ss += __shfl_xor_sync(0xffffffffu, ss, o);
    }
    float mu = s * (1.f / CC);
    float rstd = rsqrtf(ss * (1.f / CC) - mu * mu + 1e-5f);
    __nv_bfloat16* ophi = oh + (size_t)m * CC;
    __nv_bfloat16* oplo = ol + (size_t)m * CC;
    #pragma unroll
    for (int j = 0; j < 6; j++) {
        int c = lane + 32*j;
        float f = (v[j] - mu) * rstd * g[c] + bta[c];
        __nv_bfloat16 h = __float2bfloat16_rn(f);
        ophi[c] = h;
        oplo[c] = __float2bfloat16_rn(f - __bfloat162float(h));
    }
}

// ====================== window attention (register-blocked) ======================
__global__ __launch_bounds__(128) void attn_kernel(
    const float* __restrict__ qkv,
    __nv_bfloat16* __restrict__ oh, __nv_bfloat16* __restrict__ ol,
    const float* __restrict__ rpb, int shifted)
{
    int win = blockIdx.x / NHEADS;
    int hd  = blockIdx.x % NHEADS;
    __shared__ __align__(16) float q[52][33];
    __shared__ __align__(16) float k[52][33];
    __shared__ __align__(16) float v[52][36];
    __shared__ __align__(16) float sc[52][53];
    __shared__ int lab[52];
    int tid = threadIdx.x;

    const float* base = qkv + (size_t)win * NTOK * 576 + hd * HDIM;
    for (int idx = tid; idx < NTOK * HDIM; idx += 128) {
        int i = idx >> 5, d = idx & 31;
        const float* row = base + (size_t)i * 576 + d;
        q[i][d] = row[0]   * SCALEQ;
        k[i][d] = row[192];
        v[i][d] = row[384];
    }
    for (int idx = tid; idx < 3 * 33; idx += 128) {
        q[49 + idx / 33][idx % 33] = 0.f;
        k[49 + idx / 33][idx % 33] = 0.f;
    }
    for (int idx = tid; idx < 3 * 36; idx += 128)
        v[49 + idx / 36][idx % 36] = 0.f;
    for (int idx = tid; idx < 3 * 53; idx += 128)
        sc[49 + idx / 53][idx % 53] = 0.f;
    if (shifted && tid < NTOK) {
        int wl = win & 63;
        int h = (wl >> 3) * WSZ + tid / WSZ;
        int w = (wl & 7)  * WSZ + tid % WSZ;
        int rc = (h < HH  - WSZ) ? 0 : ((h < HH  - SSHIFT) ? 1 : 2);
        int cc = (w < WW2 - WSZ) ? 0 : ((w < WW2 - SSHIFT) ? 1 : 2);
        lab[tid] = rc * 3 + cc;
    }
    __syncthreads();

    for (int t = tid; t < 169; t += 128) {
        int ti = t % 13, tj = t / 13;
        int i0 = ti * 4, j0 = tj * 4;
        float a[4][4];
        #pragma unroll
        for (int r = 0; r < 4; r++)
            #pragma unroll
            for (int c = 0; c < 4; c++) a[r][c] = 0.f;
        #pragma unroll 8
        for (int d = 0; d < HDIM; d++) {
            float qr[4], kr[4];
            #pragma unroll
            for (int r = 0; r < 4; r++) qr[r] = q[i0 + r][d];
            #pragma unroll
            for (int c = 0; c < 4; c++) kr[c] = k[j0 + c][d];
            #pragma unroll
            for (int r = 0; r < 4; r++)
                #pragma unroll
                for (int c = 0; c < 4; c++)
                    a[r][c] = fmaf(qr[r], kr[c], a[r][c]);
        }
        #pragma unroll
        for (int r = 0; r < 4; r++) {
            int i = i0 + r;
            if (i >= NTOK) break;
            int li = shifted ? lab[i] : 0;
            #pragma unroll
            for (int c = 0; c < 4; c++) {
                int j = j0 + c;
                if (j < NTOK) {
                    int ridx = (i / WSZ - j / WSZ + WSZ - 1) * (2 * WSZ - 1)
                             + (i % WSZ - j % WSZ + WSZ - 1);
                    float val = a[r][c] + rpb[ridx * NHEADS + hd];
                    if (shifted && li != lab[j]) val -= 100.f;
                    sc[i][j] = val;
                }
            }
        }
    }
    __syncthreads();

    int warp = tid >> 5, lane = tid & 31;
    for (int i = warp; i < NTOK; i += 4) {
        float a0 = (lane < NTOK)      ? sc[i][lane]      : -1e30f;
        float a1 = (lane + 32 < NTOK) ? sc[i][lane + 32] : -1e30f;
        float mx = fmaxf(a0, a1);
        #pragma unroll
        for (int o = 16; o > 0; o >>= 1) mx = fmaxf(mx, __shfl_xor_sync(0xffffffffu, mx, o));
        float e0 = (lane < NTOK)      ? __expf(a0 - mx) : 0.f;
        float e1 = (lane + 32 < NTOK) ? __expf(a1 - mx) : 0.f;
        float sum = e0 + e1;
        #pragma unroll
        for (int o = 16; o > 0; o >>= 1) sum += __shfl_xor_sync(0xffffffffu, sum, o);
        float inv = 1.f / sum;
        if (lane < NTOK)      sc[i][lane]      = e0 * inv;
        if (lane + 32 < NTOK) sc[i][lane + 32] = e1 * inv;
    }
    __syncthreads();

    if (tid < 104) {
        int i0 = (tid % 13) * 4, d0 = (tid / 13) * 4;
        float a2[4][4];
        #pragma unroll
        for (int r = 0; r < 4; r++)
            #pragma unroll
            for (int c = 0; c < 4; c++) a2[r][c] = 0.f;
        #pragma unroll 7
        for (int j = 0; j < NTOK; j++) {
            float4 vv = *(const float4*)&v[j][d0];
            float s0 = sc[i0 + 0][j], s1 = sc[i0 + 1][j];
            float s2 = sc[i0 + 2][j], s3 = sc[i0 + 3][j];
            a2[0][0] = fmaf(s0, vv.x, a2[0][0]); a2[0][1] = fmaf(s0, vv.y, a2[0][1]);
            a2[0][2] = fmaf(s0, vv.z, a2[0][2]); a2[0][3] = fmaf(s0, vv.w, a2[0][3]);
            a2[1][0] = fmaf(s1, vv.x, a2[1][0]); a2[1][1] = fmaf(s1, vv.y, a2[1][1]);
            a2[1][2] = fmaf(s1, vv.z, a2[1][2]); a2[1][3] = fmaf(s1, vv.w, a2[1][3]);
            a2[2][0] = fmaf(s2, vv.x, a2[2][0]); a2[2][1] = fmaf(s2, vv.y, a2[2][1]);
            a2[2][2] = fmaf(s2, vv.z, a2[2][2]); a2[2][3] = fmaf(s2, vv.w, a2[2][3]);
            a2[3][0] = fmaf(s3, vv.x, a2[3][0]); a2[3][1] = fmaf(s3, vv.y, a2[3][1]);
            a2[3][2] = fmaf(s3, vv.z, a2[3][2]); a2[3][3] = fmaf(s3, vv.w, a2[3][3]);
        }
        size_t ob = (size_t)win * NTOK * CC + hd * HDIM;
        #pragma unroll
        for (int r = 0; r < 4; r++) {
            int i = i0 + r;
            if (i < NTOK) {
                size_t o = ob + (size_t)i * CC + d0;
                #pragma unroll
                for (int c = 0; c < 4; c += 2) {
                    float vx = a2[r][c], vy = a2[r][c + 1];
                    __nv_bfloat16 hx = __float2bfloat16_rn(vx);
                    __nv_bfloat16 hy = __float2bfloat16_rn(vy);
                    __nv_bfloat162 hp; hp.x = hx; hp.y = hy;
                    __nv_bfloat162 lp;
                    lp.x = __float2bfloat16_rn(vx - __bfloat162float(hx));
                    lp.y = __float2bfloat16_rn(vy - __bfloat162float(hy));
                    *(__nv_bfloat162*)&oh[o + c] = hp;
                    *(__nv_bfloat162*)&ol[o + c] = lp;
                }
            }
        }
    }
}

// ====================== bf16 hi/lo GEMM: BK=32, 2-stage, 3 CTAs/SM ======================
// CTA 128x64, warp grid 4x2, warp tile 32x32, ldmatrix, 3 passes,
// in-warp pipelining: ldsm for the next pass issues under the current mma block.
#define BKK     32
#define STRD    40                  // 32 + 8 pad -> 80B rows (conflict-free LDSM)
#define OFF_AH  0
#define OFF_AL  5120
#define OFF_BH  10240
#define OFF_BL  12800
#define STAGE   15360               // elems per stage
#define GSMEM   (2 * STAGE * 2)     // 61440 bytes

// NOTE: not volatile — dependencies are carried by register constraints, so
// ptxas is free to interleave these with ldmatrix issues for latency hiding.
__device__ __forceinline__ void mma16816(float* c, const uint32_t* a, const uint32_t* b)
{
    asm("mma.sync.aligned.m16n8k16.row.col.f32.bf16.bf16.f32 "
        "{%0,%1,%2,%3}, {%4,%5,%6,%7}, {%8,%9}, {%0,%1,%2,%3};"
        : "+f"(c[0]), "+f"(c[1]), "+f"(c[2]), "+f"(c[3])
        : "r"(a[0]), "r"(a[1]), "r"(a[2]), "r"(a[3]), "r"(b[0]), "r"(b[1]));
}
__device__ __forceinline__ void ldsm_x4(uint32_t* r, uint32_t addr)
{
    asm volatile("ldmatrix.sync.aligned.m8n8.x4.shared.b16 {%0,%1,%2,%3}, [%4];"
        : "=r"(r[0]), "=r"(r[1]), "=r"(r[2]), "=r"(r[3]) : "r"(addr));
}
__device__ __forceinline__ void cp_async16(uint32_t smem, const void* gmem)
{
    asm volatile("cp.async.cg.shared.global [%0], [%1], 16;" :: "r"(smem), "l"(gmem));
}
#define CP_COMMIT()  asm volatile("cp.async.commit_group;")
#define CP_WAIT(n)   asm volatile("cp.async.wait_group %0;" :: "n"(n))

template<int EPI>
__global__ __launch_bounds__(256, 3) void gemm_bf16_kernel(
    const __nv_bfloat16* __restrict__ Ah, const __nv_bfloat16* __restrict__ Al,
    const __nv_bfloat16* __restrict__ Bh, const __nv_bfloat16* __restrict__ Bl,
    const float* __restrict__ bias, float* __restrict__ Cout,
    const float* __restrict__ resid,
    __nv_bfloat16* __restrict__ OutH, __nv_bfloat16* __restrict__ OutL,
    int N, int K, int shifted)
{
    extern __shared__ __nv_bfloat16 sm[];
    uint32_t smb = (uint32_t)__cvta_generic_to_shared(sm);
    int tid = threadIdx.x;
    int wid = tid >> 5, lane = tid & 31;
    int wr = wid >> 1, wc = wid & 1;          // 4x2 warp grid
    int g = lane >> 2, t2 = (lane & 3) * 2;
    int m0 = blockIdx.y * 128, n0 = blockIdx.x * 64;

    // cp.async loader mapping (BK=32)
    int arow = tid >> 1, aq = (tid & 1) * 2;        // A: 2 chunks per part
    int brow = tid >> 2, bq = tid & 3;              // B: 1 chunk per part
    const __nv_bfloat16* gAh = Ah + (size_t)(m0 + arow) * K + aq * 8;
    const __nv_bfloat16* gAl = Al + (size_t)(m0 + arow) * K + aq * 8;
    const __nv_bfloat16* gBh = Bh + (size_t)(n0 + brow) * K + bq * 8;
    const __nv_bfloat16* gBl = Bl + (size_t)(n0 + brow) * K + bq * 8;
    uint32_t sAh = smb + 2 * (OFF_AH + arow * STRD + aq * 8);
    uint32_t sAl = smb + 2 * (OFF_AL + arow * STRD + aq * 8);
    uint32_t sBh = smb + 2 * (OFF_BH + brow * STRD + bq * 8);
    uint32_t sBl = smb + 2 * (OFF_BL + brow * STRD + bq * 8);

    auto issue = [&](int kt) {
        uint32_t so = 2u * (uint32_t)((kt & 1) * STAGE);
        int ko = kt * BKK;
        cp_async16(sAh + so,      gAh + ko);
        cp_async16(sAh + so + 16, gAh + ko + 8);
        cp_async16(sAl + so,      gAl + ko);
        cp_async16(sAl + so + 16, gAl + ko + 8);
        cp_async16(sBh + so,      gBh + ko);
        cp_async16(sBl + so,      gBl + ko);
        CP_COMMIT();
    };

    // ldmatrix lane-address components (element offsets)
    int a_r = wr * 32 + (lane & 15);
    int a_c = (lane >> 4) * 8;
    int b_r = wc * 32 + (lane & 7) + ((lane >> 4) << 3);
    int b_c = ((lane >> 3) & 1) * 8;

    float acc[2][4][4];
    #pragma unroll
    for (int mt = 0; mt < 2; mt++)
        #pragma unroll
        for (int nt = 0; nt < 4; nt++)
            #pragma unroll
            for (int r = 0; r < 4; r++) acc[mt][nt][r] = 0.f;

    int KT = K >> 5;
    issue(0);
    if (KT > 1) issue(1);

    for (int kt = 0; kt < KT; kt++) {
        if (kt + 1 < KT) { CP_WAIT(1); } else { CP_WAIT(0); }
        __syncthreads();
        uint32_t sb = smb + 2u * (uint32_t)((kt & 1) * STAGE);
        #pragma unroll
        for (int kk = 0; kk < BKK; kk += 16) {
            uint32_t Afh[2][4], Afl[2][4], Bfh[4][2], Bfl[4][2];
            // ---- issue hi A, hi B, lo A loads up front ----
            #pragma unroll
            for (int mt = 0; mt < 2; mt++)
                ldsm_x4(Afh[mt], sb + 2 * (OFF_AH + (a_r + mt * 16) * STRD + kk + a_c));
            #pragma unroll
            for (int p = 0; p < 2; p++) {
                uint32_t r[4];
                ldsm_x4(r, sb + 2 * (OFF_BH + (b_r + p * 16) * STRD + kk + b_c));
                Bfh[2*p][0] = r[0]; Bfh[2*p][1] = r[1];
                Bfh[2*p+1][0] = r[2]; Bfh[2*p+1][1] = r[3];
            }
            #pragma unroll
            for (int mt = 0; mt < 2; mt++)
                ldsm_x4(Afl[mt], sb + 2 * (OFF_AL + (a_r + mt * 16) * STRD + kk + a_c));
            // pass 1: Ah*Bh (Afl loads drain underneath)
            #pragma unroll
            for (int mt = 0; mt < 2; mt++)
                #pragma unroll
                for (int nt = 0; nt < 4; nt++)
                    mma16816(acc[mt][nt], Afh[mt], Bfh[nt]);
            // issue lo B loads, then pass 2: Al*Bh (Bfl drains underneath)
            #pragma unroll
            for (int p = 0; p < 2; p++) {
                uint32_t r[4];
                ldsm_x4(r, sb + 2 * (OFF_BL + (b_r + p * 16) * STRD + kk + b_c));
                Bfl[2*p][0] = r[0]; Bfl[2*p][1] = r[1];
                Bfl[2*p+1][0] = r[2]; Bfl[2*p+1][1] = r[3];
            }
            #pragma unroll
            for (int mt = 0; mt < 2; mt++)
                #pragma unroll
                for (int nt = 0; nt < 4; nt++)
                    mma16816(acc[mt][nt], Afl[mt], Bfh[nt]);
            // pass 3: Ah*Bl
            #pragma unroll
            for (int mt = 0; mt < 2; mt++)
                #pragma unroll
                for (int nt = 0; nt < 4; nt++)
                    mma16816(acc[mt][nt], Afh[mt], Bfl[nt]);
        }
        __syncthreads();
        if (kt + 2 < KT) issue(kt + 2);
    }

    // ---- epilogue ----
    #pragma unroll
    for (int mt = 0; mt < 2; mt++) {
        #pragma unroll
        for (int hf = 0; hf < 2; hf++) {
            int m = m0 + wr * 32 + mt * 16 + hf * 8 + g;
            size_t orow;
            if (EPI == 1) {
                int win = m / NTOK, n = m - win * NTOK;
                int b = win >> 6, wl = win & 63;
                int hs = (wl >> 3) * WSZ + n / WSZ;
                int ws = (wl & 7)  * WSZ + n % WSZ;
                if (shifted) { hs = (hs + SSHIFT) % HH; ws = (ws + SSHIFT) % WW2; }
                orow = (((size_t)b * HH + hs) * WW2 + ws) * CC;
            } else if (EPI == 3) {
                orow = (size_t)m * CC;
            } else {
                orow = (size_t)m * N;
            }
            #pragma unroll
            for (int nt = 0; nt < 4; nt++) {
                int n = n0 + wc * 32 + nt * 8 + t2;
                float vx = acc[mt][nt][hf * 2 + 0] + bias[n];
                float vy = acc[mt][nt][hf * 2 + 1] + bias[n + 1];
                if (EPI == 2) {
                    vx = 0.5f * vx * (1.f + erff(vx * 0.70710678118654752f));
                    vy = 0.5f * vy * (1.f + erff(vy * 0.70710678118654752f));
                    __nv_bfloat16 hx = __float2bfloat16_rn(vx);
                    __nv_bfloat16 hy = __float2bfloat16_rn(vy);
                    __nv_bfloat162 hp; hp.x = hx; hp.y = hy;
                    __nv_bfloat162 lp;
                    lp.x = __float2bfloat16_rn(vx - __bfloat162float(hx));
                    lp.y = __float2bfloat16_rn(vy - __bfloat162float(hy));
                    *(__nv_bfloat162*)&OutH[orow + n] = hp;
                    *(__nv_bfloat162*)&OutL[orow + n] = lp;
                } else if (EPI == 0) {
                    float2 v = {vx, vy};
                    *(float2*)&Cout[orow + n] = v;
                } else {
                    float2 r = *(const float2*)&resid[orow + n];
                    float2 v = {r.x + vx, r.y + vy};
                    *(float2*)&Cout[orow + n] = v;
                }
            }
        }
    }
}

// ====================== launch ======================
extern "C" void kernel_launch(void* const* d_in, const int* in_sizes, int n_in,
                              void* d_out, int out_size)
{
    (void)in_sizes; (void)n_in; (void)out_size;
    const float* x     = (const float*)d_in[0];
    const float* ln1g  = (const float*)d_in[1];
    const float* ln1b  = (const float*)d_in[2];
    const float* qkvw  = (const float*)d_in[3];
    const float* qkvb  = (const float*)d_in[4];
    const float* rpb   = (const float*)d_in[5];
    const float* projw = (const float*)d_in[6];
    const float* projb = (const float*)d_in[7];
    const float* ln2g  = (const float*)d_in[8];
    const float* ln2b  = (const float*)d_in[9];
    const float* fc1w  = (const float*)d_in[10];
    const float* fc1b  = (const float*)d_in[11];
    const float* fc2w  = (const float*)d_in[12];
    const float* fc2b  = (const float*)d_in[13];
    float* out = (float*)d_out;

    float *X, *QKV;
    __nv_bfloat16 *Ah, *Al, *H1h, *H1l;
    cudaGetSymbolAddress((void**)&X,   g_X);
    cudaGetSymbolAddress((void**)&QKV, g_QKV);
    cudaGetSymbolAddress((void**)&Ah,  g_Ah);
    cudaGetSymbolAddress((void**)&Al,  g_Al);
    cudaGetSymbolAddress((void**)&H1h, g_H1h);
    cudaGetSymbolAddress((void**)&H1l, g_H1l);

    __nv_bfloat16 *Wqh, *Wql, *Wph, *Wpl, *W1h, *W1l, *W2h, *W2l;
    cudaGetSymbolAddress((void**)&Wqh, g_Wqkv_h); cudaGetSymbolAddress((void**)&Wql, g_Wqkv_l);
    cudaGetSymbolAddress((void**)&Wph, g_Wprj_h); cudaGetSymbolAddress((void**)&Wpl, g_Wprj_l);
    cudaGetSymbolAddress((void**)&W1h, g_Wfc1_h); cudaGetSymbolAddress((void**)&W1l, g_Wfc1_l);
    cudaGetSymbolAddress((void**)&W2h, g_Wfc2_h); cudaGetSymbolAddress((void**)&W2l, g_Wfc2_l);

    cudaFuncSetAttribute(gemm_bf16_kernel<0>, cudaFuncAttributeMaxDynamicSharedMemorySize, GSMEM);
    cudaFuncSetAttribute(gemm_bf16_kernel<1>, cudaFuncAttributeMaxDynamicSharedMemorySize, GSMEM);
    cudaFuncSetAttribute(gemm_bf16_kernel<2>, cudaFuncAttributeMaxDynamicSharedMemorySize, GSMEM);
    cudaFuncSetAttribute(gemm_bf16_kernel<3>, cudaFuncAttributeMaxDynamicSharedMemorySize, GSMEM);

    for (int layer = 0; layer < 2; layer++) {
        size_t oq = (size_t)layer * 192 * 576;
        size_t op = (size_t)layer * 192 * 192;
        size_t o1 = (size_t)layer * 192 * 768;
        size_t o2 = (size_t)layer * 768 * 192;
        wsplit_layer_kernel<<<1728, 256>>>(
            qkvw + oq, projw + op, fc1w + o1, fc2w + o2,
            Wqh + oq, Wql + oq, Wph + op, Wpl + op,
            W1h + o1, W1l + o1, W2h + o2, W2l + o2);
    }

    const int MB = TTOT / 128;  // 1568
    for (int layer = 0; layer < 2; layer++) {
        int shifted = layer & 1;
        size_t oq = (size_t)layer * 192 * 576;
        size_t op = (size_t)layer * 192 * 192;
        size_t o1 = (size_t)layer * 192 * 768;
        size_t o2 = (size_t)layer * 768 * 192;
        const float* pre = (layer == 0) ? x : X;
        float* fc2_out   = (layer == 0) ? X : out;

        lnsplit_kernel<<<TTOT / 8, 256>>>(pre, Ah, Al,
            ln1g + layer * CC, ln1b + layer * CC, 1, shifted);
        gemm_bf16_kernel<0><<<dim3(9, MB), 256, GSMEM>>>(
            Ah, Al, Wqh + oq, Wql + oq, qkvb + layer * 576, QKV,
            nullptr, nullptr, nullptr, 576, 192, 0);
        attn_kernel<<<NWINS * NHEADS, 128>>>(QKV, Ah, Al, rpb + layer * 169 * NHEADS, shifted);
        gemm_bf16_kernel<1><<<dim3(3, MB), 256, GSMEM>>>(
            Ah, Al, Wph + op, Wpl + op, projb + layer * CC, X,
            pre, nullptr, nullptr, 192, 192, shifted);
        lnsplit_kernel<<<TTOT / 8, 256>>>(X, Ah, Al,
            ln2g + layer * CC, ln2b + layer * CC, 0, 0);
        gemm_bf16_kernel<2><<<dim3(12, MB), 256, GSMEM>>>(
            Ah, Al, W1h + o1, W1l + o1, fc1b + layer * HIDDIM, nullptr,
            nullptr, H1h, H1l, 768, 192, 0);
        gemm_bf16_kernel<3><<<dim3(3, MB), 256, GSMEM>>>(
            H1h, H1l, W2h + o2, W2l + o2, fc2b + layer * CC, fc2_out,
            X, nullptr, nullptr, 192, 768, 0);
    }
}

// round 13
// speedup vs baseline: 2.1069x; 1.1530x over previous
#include <cuda_runtime.h>
#include <cuda_fp16.h>
#include <math.h>
#include <cstdint>

// ---------------- problem constants ----------------
#define HH      56
#define WW2     56
#define CC      192
#define NHEADS  6
#define WSZ     7
#define SSHIFT  3
#define HIDDIM  768
#define NTOK    49
#define HDIM    32
#define NWINS   4096
#define TTOT    200704
#define SCALEQ  0.17677669529663687f

// ---------------- scratch ----------------
__device__ float g_X  [(size_t)TTOT * CC];          // residual stream fp32
__device__ float g_QKV[(size_t)TTOT * 3 * CC];      // qkv fp32 (window order)
__device__ __half g_Ah [(size_t)TTOT * CC];         // activation hi (GEMM A)
__device__ __half g_Al [(size_t)TTOT * CC];         // activation lo
__device__ __half g_H1h[(size_t)TTOT * HIDDIM];     // MLP hidden hi
__device__ __half g_H1l[(size_t)TTOT * HIDDIM];     // MLP hidden lo

// weights truncated to fp16, transposed to [N][K]
__device__ __half g_Wqkv[2 * 576 * 192];
__device__ __half g_Wprj[2 * 192 * 192];
__device__ __half g_Wfc1[2 * 768 * 192];
__device__ __half g_Wfc2[2 * 192 * 768];

// ====================== weight transpose + fp16 truncate (one layer) ======================
__global__ __launch_bounds__(256) void wsplit_layer_kernel(
    const float* __restrict__ qkvw, const float* __restrict__ projw,
    const float* __restrict__ fc1w, const float* __restrict__ fc2w,
    __half* __restrict__ qo, __half* __restrict__ po,
    __half* __restrict__ f1o, __half* __restrict__ f2o)
{
    int idx = blockIdx.x * 256 + threadIdx.x;
    const float* W; __half* Op; int K, N, off;
    if (idx < 110592)       { W = qkvw; Op = qo;  K = 192; N = 576; off = idx; }
    else if (idx < 147456)  { W = projw; Op = po; K = 192; N = 192; off = idx - 110592; }
    else if (idx < 294912)  { W = fc1w; Op = f1o; K = 192; N = 768; off = idx - 147456; }
    else if (idx < 442368)  { W = fc2w; Op = f2o; K = 768; N = 192; off = idx - 294912; }
    else return;
    int k = off / N, n = off - k * N;
    Op[(size_t)n * K + k] = __float2half_rn(W[off]);
}

// ====================== LN + (optional window gather) + fp16 hi/lo split ======================
__global__ __launch_bounds__(256) void lnsplit_kernel(
    const float* __restrict__ src,
    __half* __restrict__ oh, __half* __restrict__ ol,
    const float* __restrict__ g, const float* __restrict__ bta,
    int gather, int shifted)
{
    int warp = threadIdx.x >> 5, lane = threadIdx.x & 31;
    int m = blockIdx.x * 8 + warp;
    size_t tok;
    if (gather) {
        int win = m / NTOK, n = m - win * NTOK;
        int b = win >> 6, wl = win & 63;
        int hs = (wl >> 3) * WSZ + n / WSZ;
        int ws = (wl & 7)  * WSZ + n % WSZ;
        if (shifted) { hs = (hs + SSHIFT) % HH; ws = (ws + SSHIFT) % WW2; }
        tok = ((size_t)b * HH + hs) * WW2 + ws;
    } else {
        tok = (size_t)m;
    }
    const float* xp = src + tok * CC;
    float v[6]; float s = 0.f, ss = 0.f;
    #pragma unroll
    for (int j = 0; j < 6; j++) { v[j] = xp[lane + 32*j]; s += v[j]; ss += v[j]*v[j]; }
    #pragma unroll
    for (int o = 16; o > 0; o >>= 1) {
        s  += __shfl_xor_sync(0xffffffffu, s,  o);
        ss += __shfl_xor_sync(0xffffffffu, ss, o);
    }
    float mu = s * (1.f / CC);
    float rstd = rsqrtf(ss * (1.f / CC) - mu * mu + 1e-5f);
    __half* ophi = oh + (size_t)m * CC;
    __half* oplo = ol + (size_t)m * CC;
    #pragma unroll
    for (int j = 0; j < 6; j++) {
        int c = lane + 32*j;
        float f = (v[j] - mu) * rstd * g[c] + bta[c];
        __half h = __float2half_rn(f);
        ophi[c] = h;
        oplo[c] = __float2half_rn(f - __half2float(h));
    }
}

// ====================== window attention (register-blocked) ======================
__global__ __launch_bounds__(128) void attn_kernel(
    const float* __restrict__ qkv,
    __half* __restrict__ oh, __half* __restrict__ ol,
    const float* __restrict__ rpb, int shifted)
{
    int win = blockIdx.x / NHEADS;
    int hd  = blockIdx.x % NHEADS;
    __shared__ __align__(16) float q[52][33];
    __shared__ __align__(16) float k[52][33];
    __shared__ __align__(16) float v[52][36];
    __shared__ __align__(16) float sc[52][53];
    __shared__ int lab[52];
    int tid = threadIdx.x;

    const float* base = qkv + (size_t)win * NTOK * 576 + hd * HDIM;
    for (int idx = tid; idx < NTOK * HDIM; idx += 128) {
        int i = idx >> 5, d = idx & 31;
        const float* row = base + (size_t)i * 576 + d;
        q[i][d] = row[0]   * SCALEQ;
        k[i][d] = row[192];
        v[i][d] = row[384];
    }
    for (int idx = tid; idx < 3 * 33; idx += 128) {
        q[49 + idx / 33][idx % 33] = 0.f;
        k[49 + idx / 33][idx % 33] = 0.f;
    }
    for (int idx = tid; idx < 3 * 36; idx += 128)
        v[49 + idx / 36][idx % 36] = 0.f;
    for (int idx = tid; idx < 3 * 53; idx += 128)
        sc[49 + idx / 53][idx % 53] = 0.f;
    if (shifted && tid < NTOK) {
        int wl = win & 63;
        int h = (wl >> 3) * WSZ + tid / WSZ;
        int w = (wl & 7)  * WSZ + tid % WSZ;
        int rc = (h < HH  - WSZ) ? 0 : ((h < HH  - SSHIFT) ? 1 : 2);
        int cc = (w < WW2 - WSZ) ? 0 : ((w < WW2 - SSHIFT) ? 1 : 2);
        lab[tid] = rc * 3 + cc;
    }
    __syncthreads();

    for (int t = tid; t < 169; t += 128) {
        int ti = t % 13, tj = t / 13;
        int i0 = ti * 4, j0 = tj * 4;
        float a[4][4];
        #pragma unroll
        for (int r = 0; r < 4; r++)
            #pragma unroll
            for (int c = 0; c < 4; c++) a[r][c] = 0.f;
        #pragma unroll 8
        for (int d = 0; d < HDIM; d++) {
            float qr[4], kr[4];
            #pragma unroll
            for (int r = 0; r < 4; r++) qr[r] = q[i0 + r][d];
            #pragma unroll
            for (int c = 0; c < 4; c++) kr[c] = k[j0 + c][d];
            #pragma unroll
            for (int r = 0; r < 4; r++)
                #pragma unroll
                for (int c = 0; c < 4; c++)
                    a[r][c] = fmaf(qr[r], kr[c], a[r][c]);
        }
        #pragma unroll
        for (int r = 0; r < 4; r++) {
            int i = i0 + r;
            if (i >= NTOK) break;
            int li = shifted ? lab[i] : 0;
            #pragma unroll
            for (int c = 0; c < 4; c++) {
                int j = j0 + c;
                if (j < NTOK) {
                    int ridx = (i / WSZ - j / WSZ + WSZ - 1) * (2 * WSZ - 1)
                             + (i % WSZ - j % WSZ + WSZ - 1);
                    float val = a[r][c] + rpb[ridx * NHEADS + hd];
                    if (shifted && li != lab[j]) val -= 100.f;
                    sc[i][j] = val;
                }
            }
        }
    }
    __syncthreads();

    int warp = tid >> 5, lane = tid & 31;
    for (int i = warp; i < NTOK; i += 4) {
        float a0 = (lane < NTOK)      ? sc[i][lane]      : -1e30f;
        float a1 = (lane + 32 < NTOK) ? sc[i][lane + 32] : -1e30f;
        float mx = fmaxf(a0, a1);
        #pragma unroll
        for (int o = 16; o > 0; o >>= 1) mx = fmaxf(mx, __shfl_xor_sync(0xffffffffu, mx, o));
        float e0 = (lane < NTOK)      ? __expf(a0 - mx) : 0.f;
        float e1 = (lane + 32 < NTOK) ? __expf(a1 - mx) : 0.f;
        float sum = e0 + e1;
        #pragma unroll
        for (int o = 16; o > 0; o >>= 1) sum += __shfl_xor_sync(0xffffffffu, sum, o);
        float inv = 1.f / sum;
        if (lane < NTOK)      sc[i][lane]      = e0 * inv;
        if (lane + 32 < NTOK) sc[i][lane + 32] = e1 * inv;
    }
    __syncthreads();

    if (tid < 104) {
        int i0 = (tid % 13) * 4, d0 = (tid / 13) * 4;
        float a2[4][4];
        #pragma unroll
        for (int r = 0; r < 4; r++)
            #pragma unroll
            for (int c = 0; c < 4; c++) a2[r][c] = 0.f;
        #pragma unroll 7
        for (int j = 0; j < NTOK; j++) {
            float4 vv = *(const float4*)&v[j][d0];
            float s0 = sc[i0 + 0][j], s1 = sc[i0 + 1][j];
            float s2 = sc[i0 + 2][j], s3 = sc[i0 + 3][j];
            a2[0][0] = fmaf(s0, vv.x, a2[0][0]); a2[0][1] = fmaf(s0, vv.y, a2[0][1]);
            a2[0][2] = fmaf(s0, vv.z, a2[0][2]); a2[0][3] = fmaf(s0, vv.w, a2[0][3]);
            a2[1][0] = fmaf(s1, vv.x, a2[1][0]); a2[1][1] = fmaf(s1, vv.y, a2[1][1]);
            a2[1][2] = fmaf(s1, vv.z, a2[1][2]); a2[1][3] = fmaf(s1, vv.w, a2[1][3]);
            a2[2][0] = fmaf(s2, vv.x, a2[2][0]); a2[2][1] = fmaf(s2, vv.y, a2[2][1]);
            a2[2][2] = fmaf(s2, vv.z, a2[2][2]); a2[2][3] = fmaf(s2, vv.w, a2[2][3]);
            a2[3][0] = fmaf(s3, vv.x, a2[3][0]); a2[3][1] = fmaf(s3, vv.y, a2[3][1]);
            a2[3][2] = fmaf(s3, vv.z, a2[3][2]); a2[3][3] = fmaf(s3, vv.w, a2[3][3]);
        }
        size_t ob = (size_t)win * NTOK * CC + hd * HDIM;
        #pragma unroll
        for (int r = 0; r < 4; r++) {
            int i = i0 + r;
            if (i < NTOK) {
                size_t o = ob + (size_t)i * CC + d0;
                #pragma unroll
                for (int c = 0; c < 4; c += 2) {
                    float vx = a2[r][c], vy = a2[r][c + 1];
                    __half hx = __float2half_rn(vx);
                    __half hy = __float2half_rn(vy);
                    __half2 hp; hp.x = hx; hp.y = hy;
                    __half2 lp;
                    lp.x = __float2half_rn(vx - __half2float(hx));
                    lp.y = __float2half_rn(vy - __half2float(hy));
                    *(__half2*)&oh[o + c] = hp;
                    *(__half2*)&ol[o + c] = lp;
                }
            }
        }
    }
}

// ====================== fp16 hi/lo GEMM: BK=32, 2-stage, 3 CTAs/SM, 2 passes ======================
// C = (Ah+Al)[M,K] @ B[N,K]^T + bias.  CTA 128x64, warp grid 4x2, warp tile 32x32.
#define BKK     32
#define STRD    40                  // 32 + 8 pad -> 80B rows (conflict-free LDSM)
#define OFF_AH  0
#define OFF_AL  5120
#define OFF_BH  10240
#define STAGE   12800               // elems per stage
#define GSMEM   (2 * STAGE * 2)     // 51200 bytes

__device__ __forceinline__ void mma16816(float* c, const uint32_t* a, const uint32_t* b)
{
    asm("mma.sync.aligned.m16n8k16.row.col.f32.f16.f16.f32 "
        "{%0,%1,%2,%3}, {%4,%5,%6,%7}, {%8,%9}, {%0,%1,%2,%3};"
        : "+f"(c[0]), "+f"(c[1]), "+f"(c[2]), "+f"(c[3])
        : "r"(a[0]), "r"(a[1]), "r"(a[2]), "r"(a[3]), "r"(b[0]), "r"(b[1]));
}
__device__ __forceinline__ void ldsm_x4(uint32_t* r, uint32_t addr)
{
    asm volatile("ldmatrix.sync.aligned.m8n8.x4.shared.b16 {%0,%1,%2,%3}, [%4];"
        : "=r"(r[0]), "=r"(r[1]), "=r"(r[2]), "=r"(r[3]) : "r"(addr));
}
__device__ __forceinline__ void cp_async16(uint32_t smem, const void* gmem)
{
    asm volatile("cp.async.cg.shared.global [%0], [%1], 16;" :: "r"(smem), "l"(gmem));
}
#define CP_COMMIT()  asm volatile("cp.async.commit_group;")
#define CP_WAIT(n)   asm volatile("cp.async.wait_group %0;" :: "n"(n))

template<int EPI>
__global__ __launch_bounds__(256, 3) void gemm_fp16_kernel(
    const __half* __restrict__ Ah, const __half* __restrict__ Al,
    const __half* __restrict__ Bh,
    const float* __restrict__ bias, float* __restrict__ Cout,
    const float* __restrict__ resid,
    __half* __restrict__ OutH, __half* __restrict__ OutL,
    int N, int K, int shifted)
{
    extern __shared__ __half sm[];
    uint32_t smb = (uint32_t)__cvta_generic_to_shared(sm);
    int tid = threadIdx.x;
    int wid = tid >> 5, lane = tid & 31;
    int wr = wid >> 1, wc = wid & 1;          // 4x2 warp grid
    int g = lane >> 2, t2 = (lane & 3) * 2;
    int m0 = blockIdx.y * 128, n0 = blockIdx.x * 64;

    // cp.async loader mapping (BK=32)
    int arow = tid >> 1, aq = (tid & 1) * 2;        // A: 2 chunks per part
    int brow = tid >> 2, bq = tid & 3;              // B: 1 chunk
    const __half* gAh = Ah + (size_t)(m0 + arow) * K + aq * 8;
    const __half* gAl = Al + (size_t)(m0 + arow) * K + aq * 8;
    const __half* gBh = Bh + (size_t)(n0 + brow) * K + bq * 8;
    uint32_t sAh = smb + 2 * (OFF_AH + arow * STRD + aq * 8);
    uint32_t sAl = smb + 2 * (OFF_AL + arow * STRD + aq * 8);
    uint32_t sBh = smb + 2 * (OFF_BH + brow * STRD + bq * 8);

    auto issue = [&](int kt) {
        uint32_t so = 2u * (uint32_t)((kt & 1) * STAGE);
        int ko = kt * BKK;
        cp_async16(sAh + so,      gAh + ko);
        cp_async16(sAh + so + 16, gAh + ko + 8);
        cp_async16(sAl + so,      gAl + ko);
        cp_async16(sAl + so + 16, gAl + ko + 8);
        cp_async16(sBh + so,      gBh + ko);
        CP_COMMIT();
    };

    // ldmatrix lane-address components (element offsets)
    int a_r = wr * 32 + (lane & 15);
    int a_c = (lane >> 4) * 8;
    int b_r = wc * 32 + (lane & 7) + ((lane >> 4) << 3);
    int b_c = ((lane >> 3) & 1) * 8;

    float acc[2][4][4];
    #pragma unroll
    for (int mt = 0; mt < 2; mt++)
        #pragma unroll
        for (int nt = 0; nt < 4; nt++)
            #pragma unroll
            for (int r = 0; r < 4; r++) acc[mt][nt][r] = 0.f;

    int KT = K >> 5;
    issue(0);
    if (KT > 1) issue(1);

    for (int kt = 0; kt < KT; kt++) {
        if (kt + 1 < KT) { CP_WAIT(1); } else { CP_WAIT(0); }
        __syncthreads();
        uint32_t sb = smb + 2u * (uint32_t)((kt & 1) * STAGE);
        #pragma unroll
        for (int kk = 0; kk < BKK; kk += 16) {
            uint32_t Afh[2][4], Afl[2][4], Bf[4][2];
            #pragma unroll
            for (int mt = 0; mt < 2; mt++)
                ldsm_x4(Afh[mt], sb + 2 * (OFF_AH + (a_r + mt * 16) * STRD + kk + a_c));
            #pragma unroll
            for (int p = 0; p < 2; p++) {
                uint32_t r[4];
                ldsm_x4(r, sb + 2 * (OFF_BH + (b_r + p * 16) * STRD + kk + b_c));
                Bf[2*p][0] = r[0]; Bf[2*p][1] = r[1];
                Bf[2*p+1][0] = r[2]; Bf[2*p+1][1] = r[3];
            }
            #pragma unroll
            for (int mt = 0; mt < 2; mt++)
                ldsm_x4(Afl[mt], sb + 2 * (OFF_AL + (a_r + mt * 16) * STRD + kk + a_c));
            // pass 1: Ah*B  (Afl drains underneath)
            #pragma unroll
            for (int mt = 0; mt < 2; mt++)
                #pragma unroll
                for (int nt = 0; nt < 4; nt++)
                    mma16816(acc[mt][nt], Afh[mt], Bf[nt]);
            // pass 2: Al*B
            #pragma unroll
            for (int mt = 0; mt < 2; mt++)
                #pragma unroll
                for (int nt = 0; nt < 4; nt++)
                    mma16816(acc[mt][nt], Afl[mt], Bf[nt]);
        }
        __syncthreads();
        if (kt + 2 < KT) issue(kt + 2);
    }

    // ---- epilogue ----
    #pragma unroll
    for (int mt = 0; mt < 2; mt++) {
        #pragma unroll
        for (int hf = 0; hf < 2; hf++) {
            int m = m0 + wr * 32 + mt * 16 + hf * 8 + g;
            size_t orow;
            if (EPI == 1) {
                int win = m / NTOK, n = m - win * NTOK;
                int b = win >> 6, wl = win & 63;
                int hs = (wl >> 3) * WSZ + n / WSZ;
                int ws = (wl & 7)  * WSZ + n % WSZ;
                if (shifted) { hs = (hs + SSHIFT) % HH; ws = (ws + SSHIFT) % WW2; }
                orow = (((size_t)b * HH + hs) * WW2 + ws) * CC;
            } else if (EPI == 3) {
                orow = (size_t)m * CC;
            } else {
                orow = (size_t)m * N;
            }
            #pragma unroll
            for (int nt = 0; nt < 4; nt++) {
                int n = n0 + wc * 32 + nt * 8 + t2;
                float vx = acc[mt][nt][hf * 2 + 0] + bias[n];
                float vy = acc[mt][nt][hf * 2 + 1] + bias[n + 1];
                if (EPI == 2) {
                    vx = 0.5f * vx * (1.f + erff(vx * 0.70710678118654752f));
                    vy = 0.5f * vy * (1.f + erff(vy * 0.70710678118654752f));
                    __half hx = __float2half_rn(vx);
                    __half hy = __float2half_rn(vy);
                    __half2 hp; hp.x = hx; hp.y = hy;
                    __half2 lp;
                    lp.x = __float2half_rn(vx - __half2float(hx));
                    lp.y = __float2half_rn(vy - __half2float(hy));
                    *(__half2*)&OutH[orow + n] = hp;
                    *(__half2*)&OutL[orow + n] = lp;
                } else if (EPI == 0) {
                    float2 v = {vx, vy};
                    *(float2*)&Cout[orow + n] = v;
                } else {
                    float2 r = *(const float2*)&resid[orow + n];
                    float2 v = {r.x + vx, r.y + vy};
                    *(float2*)&Cout[orow + n] = v;
                }
            }
        }
    }
}

// ====================== launch ======================
extern "C" void kernel_launch(void* const* d_in, const int* in_sizes, int n_in,
                              void* d_out, int out_size)
{
    (void)in_sizes; (void)n_in; (void)out_size;
    const float* x     = (const float*)d_in[0];
    const float* ln1g  = (const float*)d_in[1];
    const float* ln1b  = (const float*)d_in[2];
    const float* qkvw  = (const float*)d_in[3];
    const float* qkvb  = (const float*)d_in[4];
    const float* rpb   = (const float*)d_in[5];
    const float* projw = (const float*)d_in[6];
    const float* projb = (const float*)d_in[7];
    const float* ln2g  = (const float*)d_in[8];
    const float* ln2b  = (const float*)d_in[9];
    const float* fc1w  = (const float*)d_in[10];
    const float* fc1b  = (const float*)d_in[11];
    const float* fc2w  = (const float*)d_in[12];
    const float* fc2b  = (const float*)d_in[13];
    float* out = (float*)d_out;

    float *X, *QKV;
    __half *Ah, *Al, *H1h, *H1l;
    cudaGetSymbolAddress((void**)&X,   g_X);
    cudaGetSymbolAddress((void**)&QKV, g_QKV);
    cudaGetSymbolAddress((void**)&Ah,  g_Ah);
    cudaGetSymbolAddress((void**)&Al,  g_Al);
    cudaGetSymbolAddress((void**)&H1h, g_H1h);
    cudaGetSymbolAddress((void**)&H1l, g_H1l);

    __half *Wq, *Wp, *W1, *W2;
    cudaGetSymbolAddress((void**)&Wq, g_Wqkv);
    cudaGetSymbolAddress((void**)&Wp, g_Wprj);
    cudaGetSymbolAddress((void**)&W1, g_Wfc1);
    cudaGetSymbolAddress((void**)&W2, g_Wfc2);

    cudaFuncSetAttribute(gemm_fp16_kernel<0>, cudaFuncAttributeMaxDynamicSharedMemorySize, GSMEM);
    cudaFuncSetAttribute(gemm_fp16_kernel<1>, cudaFuncAttributeMaxDynamicSharedMemorySize, GSMEM);
    cudaFuncSetAttribute(gemm_fp16_kernel<2>, cudaFuncAttributeMaxDynamicSharedMemorySize, GSMEM);
    cudaFuncSetAttribute(gemm_fp16_kernel<3>, cudaFuncAttributeMaxDynamicSharedMemorySize, GSMEM);

    for (int layer = 0; layer < 2; layer++) {
        size_t oq = (size_t)layer * 192 * 576;
        size_t op = (size_t)layer * 192 * 192;
        size_t o1 = (size_t)layer * 192 * 768;
        size_t o2 = (size_t)layer * 768 * 192;
        wsplit_layer_kernel<<<1728, 256>>>(
            qkvw + oq, projw + op, fc1w + o1, fc2w + o2,
            Wq + oq, Wp + op, W1 + o1, W2 + o2);
    }

    const int MB = TTOT / 128;  // 1568
    for (int layer = 0; layer < 2; layer++) {
        int shifted = layer & 1;
        size_t oq = (size_t)layer * 192 * 576;
        size_t op = (size_t)layer * 192 * 192;
        size_t o1 = (size_t)layer * 192 * 768;
        size_t o2 = (size_t)layer * 768 * 192;
        const float* pre = (layer == 0) ? x : X;
        float* fc2_out   = (layer == 0) ? X : out;

        lnsplit_kernel<<<TTOT / 8, 256>>>(pre, Ah, Al,
            ln1g + layer * CC, ln1b + layer * CC, 1, shifted);
        gemm_fp16_kernel<0><<<dim3(9, MB), 256, GSMEM>>>(
            Ah, Al, Wq + oq, qkvb + layer * 576, QKV,
            nullptr, nullptr, nullptr, 576, 192, 0);
        attn_kernel<<<NWINS * NHEADS, 128>>>(QKV, Ah, Al, rpb + layer * 169 * NHEADS, shifted);
        gemm_fp16_kernel<1><<<dim3(3, MB), 256, GSMEM>>>(
            Ah, Al, Wp + op, projb + layer * CC, X,
            pre, nullptr, nullptr, 192, 192, shifted);
        lnsplit_kernel<<<TTOT / 8, 256>>>(X, Ah, Al,
            ln2g + layer * CC, ln2b + layer * CC, 0, 0);
        gemm_fp16_kernel<2><<<dim3(12, MB), 256, GSMEM>>>(
            Ah, Al, W1 + o1, fc1b + layer * HIDDIM, nullptr,
            nullptr, H1h, H1l, 768, 192, 0);
        gemm_fp16_kernel<3><<<dim3(3, MB), 256, GSMEM>>>(
            H1h, H1l, W2 + o2, fc2b + layer * CC, fc2_out,
            X, nullptr, nullptr, 192, 768, 0);
    }
}

// round 15
// speedup vs baseline: 3.0290x; 1.4376x over previous
#include <cuda_runtime.h>
#include <cuda_fp16.h>
#include <math.h>
#include <cstdint>

// ---------------- problem constants ----------------
#define HH      56
#define WW2     56
#define CC      192
#define NHEADS  6
#define WSZ     7
#define SSHIFT  3
#define HIDDIM  768
#define NTOK    49
#define HDIM    32
#define NWINS   4096
#define TTOT    200704
#define SCALEQ  0.17677669529663687f

// ---------------- scratch ----------------
__device__ float  g_X  [(size_t)TTOT * CC];         // residual stream fp32
__device__ __half g_QKV[(size_t)TTOT * 3 * CC];     // qkv fp16 (window order)
__device__ __half g_A  [(size_t)TTOT * CC];         // activation fp16 (GEMM A)
__device__ __half g_H1 [(size_t)TTOT * HIDDIM];     // MLP hidden fp16

// weights fp16, transposed to [N][K]
__device__ __half g_Wqkv[2 * 576 * 192];
__device__ __half g_Wprj[2 * 192 * 192];
__device__ __half g_Wfc1[2 * 768 * 192];
__device__ __half g_Wfc2[2 * 192 * 768];

// ====================== weight transpose + fp16 truncate (one layer) ======================
__global__ __launch_bounds__(256) void wsplit_layer_kernel(
    const float* __restrict__ qkvw, const float* __restrict__ projw,
    const float* __restrict__ fc1w, const float* __restrict__ fc2w,
    __half* __restrict__ qo, __half* __restrict__ po,
    __half* __restrict__ f1o, __half* __restrict__ f2o)
{
    int idx = blockIdx.x * 256 + threadIdx.x;
    const float* W; __half* Op; int K, N, off;
    if (idx < 110592)       { W = qkvw; Op = qo;  K = 192; N = 576; off = idx; }
    else if (idx < 147456)  { W = projw; Op = po; K = 192; N = 192; off = idx - 110592; }
    else if (idx < 294912)  { W = fc1w; Op = f1o; K = 192; N = 768; off = idx - 147456; }
    else if (idx < 442368)  { W = fc2w; Op = f2o; K = 768; N = 192; off = idx - 294912; }
    else return;
    int k = off / N, n = off - k * N;
    Op[(size_t)n * K + k] = __float2half_rn(W[off]);
}

// ====================== LN + (optional window gather) + fp16 store ======================
__global__ __launch_bounds__(256) void lnsplit_kernel(
    const float* __restrict__ src, __half* __restrict__ oh,
    const float* __restrict__ g, const float* __restrict__ bta,
    int gather, int shifted)
{
    int warp = threadIdx.x >> 5, lane = threadIdx.x & 31;
    int m = blockIdx.x * 8 + warp;
    size_t tok;
    if (gather) {
        int win = m / NTOK, n = m - win * NTOK;
        int b = win >> 6, wl = win & 63;
        int hs = (wl >> 3) * WSZ + n / WSZ;
        int ws = (wl & 7)  * WSZ + n % WSZ;
        if (shifted) { hs = (hs + SSHIFT) % HH; ws = (ws + SSHIFT) % WW2; }
        tok = ((size_t)b * HH + hs) * WW2 + ws;
    } else {
        tok = (size_t)m;
    }
    const float* xp = src + tok * CC;
    float v[6]; float s = 0.f, ss = 0.f;
    #pragma unroll
    for (int j = 0; j < 6; j++) { v[j] = xp[lane + 32*j]; s += v[j]; ss += v[j]*v[j]; }
    #pragma unroll
    for (int o = 16; o > 0; o >>= 1) {
        s  += __shfl_xor_sync(0xffffffffu, s,  o);
        ss += __shfl_xor_sync(0xffffffffu, ss, o);
    }
    float mu = s * (1.f / CC);
    float rstd = rsqrtf(ss * (1.f / CC) - mu * mu + 1e-5f);
    __half* op = oh + (size_t)m * CC;
    #pragma unroll
    for (int j = 0; j < 6; j++) {
        int c = lane + 32*j;
        op[c] = __float2half_rn((v[j] - mu) * rstd * g[c] + bta[c]);
    }
}

// ====================== window attention (register-blocked, fp16 I/O) ======================
__global__ __launch_bounds__(128) void attn_kernel(
    const __half* __restrict__ qkv, __half* __restrict__ oh,
    const float* __restrict__ rpb, int shifted)
{
    int win = blockIdx.x / NHEADS;
    int hd  = blockIdx.x % NHEADS;
    __shared__ __align__(16) float q[52][33];
    __shared__ __align__(16) float k[52][33];
    __shared__ __align__(16) float v[52][36];
    __shared__ __align__(16) float sc[52][53];
    __shared__ int lab[52];
    int tid = threadIdx.x;

    const __half* base = qkv + (size_t)win * NTOK * 576 + hd * HDIM;
    for (int idx = tid; idx < NTOK * HDIM; idx += 128) {
        int i = idx >> 5, d = idx & 31;
        const __half* row = base + (size_t)i * 576 + d;
        q[i][d] = __half2float(row[0])   * SCALEQ;
        k[i][d] = __half2float(row[192]);
        v[i][d] = __half2float(row[384]);
    }
    for (int idx = tid; idx < 3 * 33; idx += 128) {
        q[49 + idx / 33][idx % 33] = 0.f;
        k[49 + idx / 33][idx % 33] = 0.f;
    }
    for (int idx = tid; idx < 3 * 36; idx += 128)
        v[49 + idx / 36][idx % 36] = 0.f;
    for (int idx = tid; idx < 3 * 53; idx += 128)
        sc[49 + idx / 53][idx % 53] = 0.f;
    if (shifted && tid < NTOK) {
        int wl = win & 63;
        int h = (wl >> 3) * WSZ + tid / WSZ;
        int w = (wl & 7)  * WSZ + tid % WSZ;
        int rc = (h < HH  - WSZ) ? 0 : ((h < HH  - SSHIFT) ? 1 : 2);
        int cc = (w < WW2 - WSZ) ? 0 : ((w < WW2 - SSHIFT) ? 1 : 2);
        lab[tid] = rc * 3 + cc;
    }
    __syncthreads();

    for (int t = tid; t < 169; t += 128) {
        int ti = t % 13, tj = t / 13;
        int i0 = ti * 4, j0 = tj * 4;
        float a[4][4];
        #pragma unroll
        for (int r = 0; r < 4; r++)
            #pragma unroll
            for (int c = 0; c < 4; c++) a[r][c] = 0.f;
        #pragma unroll 8
        for (int d = 0; d < HDIM; d++) {
            float qr[4], kr[4];
            #pragma unroll
            for (int r = 0; r < 4; r++) qr[r] = q[i0 + r][d];
            #pragma unroll
            for (int c = 0; c < 4; c++) kr[c] = k[j0 + c][d];
            #pragma unroll
            for (int r = 0; r < 4; r++)
                #pragma unroll
                for (int c = 0; c < 4; c++)
                    a[r][c] = fmaf(qr[r], kr[c], a[r][c]);
        }
        #pragma unroll
        for (int r = 0; r < 4; r++) {
            int i = i0 + r;
            if (i >= NTOK) break;
            int li = shifted ? lab[i] : 0;
            #pragma unroll
            for (int c = 0; c < 4; c++) {
                int j = j0 + c;
                if (j < NTOK) {
                    int ridx = (i / WSZ - j / WSZ + WSZ - 1) * (2 * WSZ - 1)
                             + (i % WSZ - j % WSZ + WSZ - 1);
                    float val = a[r][c] + rpb[ridx * NHEADS + hd];
                    if (shifted && li != lab[j]) val -= 100.f;
                    sc[i][j] = val;
                }
            }
        }
    }
    __syncthreads();

    int warp = tid >> 5, lane = tid & 31;
    for (int i = warp; i < NTOK; i += 4) {
        float a0 = (lane < NTOK)      ? sc[i][lane]      : -1e30f;
        float a1 = (lane + 32 < NTOK) ? sc[i][lane + 32] : -1e30f;
        float mx = fmaxf(a0, a1);
        #pragma unroll
        for (int o = 16; o > 0; o >>= 1) mx = fmaxf(mx, __shfl_xor_sync(0xffffffffu, mx, o));
        float e0 = (lane < NTOK)      ? __expf(a0 - mx) : 0.f;
        float e1 = (lane + 32 < NTOK) ? __expf(a1 - mx) : 0.f;
        float sum = e0 + e1;
        #pragma unroll
        for (int o = 16; o > 0; o >>= 1) sum += __shfl_xor_sync(0xffffffffu, sum, o);
        float inv = 1.f / sum;
        if (lane < NTOK)      sc[i][lane]      = e0 * inv;
        if (lane + 32 < NTOK) sc[i][lane + 32] = e1 * inv;
    }
    __syncthreads();

    if (tid < 104) {
        int i0 = (tid % 13) * 4, d0 = (tid / 13) * 4;
        float a2[4][4];
        #pragma unroll
        for (int r = 0; r < 4; r++)
            #pragma unroll
            for (int c = 0; c < 4; c++) a2[r][c] = 0.f;
        #pragma unroll 7
        for (int j = 0; j < NTOK; j++) {
            float4 vv = *(const float4*)&v[j][d0];
            float s0 = sc[i0 + 0][j], s1 = sc[i0 + 1][j];
            float s2 = sc[i0 + 2][j], s3 = sc[i0 + 3][j];
            a2[0][0] = fmaf(s0, vv.x, a2[0][0]); a2[0][1] = fmaf(s0, vv.y, a2[0][1]);
            a2[0][2] = fmaf(s0, vv.z, a2[0][2]); a2[0][3] = fmaf(s0, vv.w, a2[0][3]);
            a2[1][0] = fmaf(s1, vv.x, a2[1][0]); a2[1][1] = fmaf(s1, vv.y, a2[1][1]);
            a2[1][2] = fmaf(s1, vv.z, a2[1][2]); a2[1][3] = fmaf(s1, vv.w, a2[1][3]);
            a2[2][0] = fmaf(s2, vv.x, a2[2][0]); a2[2][1] = fmaf(s2, vv.y, a2[2][1]);
            a2[2][2] = fmaf(s2, vv.z, a2[2][2]); a2[2][3] = fmaf(s2, vv.w, a2[2][3]);
            a2[3][0] = fmaf(s3, vv.x, a2[3][0]); a2[3][1] = fmaf(s3, vv.y, a2[3][1]);
            a2[3][2] = fmaf(s3, vv.z, a2[3][2]); a2[3][3] = fmaf(s3, vv.w, a2[3][3]);
        }
        size_t ob = (size_t)win * NTOK * CC + hd * HDIM;
        #pragma unroll
        for (int r = 0; r < 4; r++) {
            int i = i0 + r;
            if (i < NTOK) {
                size_t o = ob + (size_t)i * CC + d0;
                #pragma unroll
                for (int c = 0; c < 4; c += 2) {
                    __half2 hp;
                    hp.x = __float2half_rn(a2[r][c]);
                    hp.y = __float2half_rn(a2[r][c + 1]);
                    *(__half2*)&oh[o + c] = hp;
                }
            }
        }
    }
}

// ====================== single-pass fp16 GEMM: BK=32, 2-stage, 4 CTAs/SM ======================
// C = A[M,K] @ B[N,K]^T + bias.  CTA 128x64, warp grid 4x2, warp tile 32x32.
// EPI: 0 fp16 store; 1 win-reverse(+unshift) residual fp32; 2 GELU fp16 store; 3 residual fp32
#define BKK     32
#define STRD    40                  // 32 + 8 pad -> 80B rows (conflict-free LDSM)
#define OFF_A   0
#define OFF_B   5120
#define STAGE   7680                // elems per stage
#define GSMEM   (2 * STAGE * 2)     // 30720 bytes

__device__ __forceinline__ void mma16816(float* c, const uint32_t* a, const uint32_t* b)
{
    asm("mma.sync.aligned.m16n8k16.row.col.f32.f16.f16.f32 "
        "{%0,%1,%2,%3}, {%4,%5,%6,%7}, {%8,%9}, {%0,%1,%2,%3};"
        : "+f"(c[0]), "+f"(c[1]), "+f"(c[2]), "+f"(c[3])
        : "r"(a[0]), "r"(a[1]), "r"(a[2]), "r"(a[3]), "r"(b[0]), "r"(b[1]));
}
__device__ __forceinline__ void ldsm_x4(uint32_t* r, uint32_t addr)
{
    asm volatile("ldmatrix.sync.aligned.m8n8.x4.shared.b16 {%0,%1,%2,%3}, [%4];"
        : "=r"(r[0]), "=r"(r[1]), "=r"(r[2]), "=r"(r[3]) : "r"(addr));
}
__device__ __forceinline__ void cp_async16(uint32_t smem, const void* gmem)
{
    asm volatile("cp.async.cg.shared.global [%0], [%1], 16;" :: "r"(smem), "l"(gmem));
}
#define CP_COMMIT()  asm volatile("cp.async.commit_group;")
#define CP_WAIT(n)   asm volatile("cp.async.wait_group %0;" :: "n"(n))

template<int EPI>
__global__ __launch_bounds__(256, 4) void gemm_fp16_kernel(
    const __half* __restrict__ A, const __half* __restrict__ B,
    const float* __restrict__ bias, float* __restrict__ Cout,
    const float* __restrict__ resid, __half* __restrict__ OutH,
    int N, int K, int shifted)
{
    extern __shared__ __half sm[];
    uint32_t smb = (uint32_t)__cvta_generic_to_shared(sm);
    int tid = threadIdx.x;
    int wid = tid >> 5, lane = tid & 31;
    int wr = wid >> 1, wc = wid & 1;          // 4x2 warp grid
    int g = lane >> 2, t2 = (lane & 3) * 2;
    int m0 = blockIdx.y * 128, n0 = blockIdx.x * 64;

    // cp.async loader mapping (BK=32)
    int arow = tid >> 1, aq = (tid & 1) * 2;        // A: 2 chunks/thread
    int brow = tid >> 2, bq = tid & 3;              // B: 1 chunk/thread
    const __half* gA = A + (size_t)(m0 + arow) * K + aq * 8;
    const __half* gB = B + (size_t)(n0 + brow) * K + bq * 8;
    uint32_t sA = smb + 2 * (OFF_A + arow * STRD + aq * 8);
    uint32_t sB = smb + 2 * (OFF_B + brow * STRD + bq * 8);

    auto issue = [&](int kt) {
        uint32_t so = 2u * (uint32_t)((kt & 1) * STAGE);
        int ko = kt * BKK;
        cp_async16(sA + so,      gA + ko);
        cp_async16(sA + so + 16, gA + ko + 8);
        cp_async16(sB + so,      gB + ko);
        CP_COMMIT();
    };

    // ldmatrix lane-address components (element offsets)
    int a_r = wr * 32 + (lane & 15);
    int a_c = (lane >> 4) * 8;
    int b_r = wc * 32 + (lane & 7) + ((lane >> 4) << 3);
    int b_c = ((lane >> 3) & 1) * 8;

    float acc[2][4][4];
    #pragma unroll
    for (int mt = 0; mt < 2; mt++)
        #pragma unroll
        for (int nt = 0; nt < 4; nt++)
            #pragma unroll
            for (int r = 0; r < 4; r++) acc[mt][nt][r] = 0.f;

    int KT = K >> 5;
    issue(0);
    if (KT > 1) issue(1);

    for (int kt = 0; kt < KT; kt++) {
        if (kt + 1 < KT) { CP_WAIT(1); } else { CP_WAIT(0); }
        __syncthreads();
        uint32_t sb = smb + 2u * (uint32_t)((kt & 1) * STAGE);
        #pragma unroll
        for (int kk = 0; kk < BKK; kk += 16) {
            uint32_t Af[2][4], Bf[4][2];
            #pragma unroll
            for (int mt = 0; mt < 2; mt++)
                ldsm_x4(Af[mt], sb + 2 * (OFF_A + (a_r + mt * 16) * STRD + kk + a_c));
            #pragma unroll
            for (int p = 0; p < 2; p++) {
                uint32_t r[4];
                ldsm_x4(r, sb + 2 * (OFF_B + (b_r + p * 16) * STRD + kk + b_c));
                Bf[2*p][0] = r[0]; Bf[2*p][1] = r[1];
                Bf[2*p+1][0] = r[2]; Bf[2*p+1][1] = r[3];
            }
            #pragma unroll
            for (int mt = 0; mt < 2; mt++)
                #pragma unroll
                for (int nt = 0; nt < 4; nt++)
                    mma16816(acc[mt][nt], Af[mt], Bf[nt]);
        }
        __syncthreads();
        if (kt + 2 < KT) issue(kt + 2);
    }

    // ---- epilogue ----
    #pragma unroll
    for (int mt = 0; mt < 2; mt++) {
        #pragma unroll
        for (int hf = 0; hf < 2; hf++) {
            int m = m0 + wr * 32 + mt * 16 + hf * 8 + g;
            size_t orow;
            if (EPI == 1) {
                int win = m / NTOK, n = m - win * NTOK;
                int b = win >> 6, wl = win & 63;
                int hs = (wl >> 3) * WSZ + n / WSZ;
                int ws = (wl & 7)  * WSZ + n % WSZ;
                if (shifted) { hs = (hs + SSHIFT) % HH; ws = (ws + SSHIFT) % WW2; }
                orow = (((size_t)b * HH + hs) * WW2 + ws) * CC;
            } else if (EPI == 3) {
                orow = (size_t)m * CC;
            } else {
                orow = (size_t)m * N;
            }
            #pragma unroll
            for (int nt = 0; nt < 4; nt++) {
                int n = n0 + wc * 32 + nt * 8 + t2;
                float vx = acc[mt][nt][hf * 2 + 0] + bias[n];
                float vy = acc[mt][nt][hf * 2 + 1] + bias[n + 1];
                if (EPI == 2) {
                    vx = 0.5f * vx * (1.f + erff(vx * 0.70710678118654752f));
                    vy = 0.5f * vy * (1.f + erff(vy * 0.70710678118654752f));
                }
                if (EPI == 0 || EPI == 2) {
                    __half2 hp;
                    hp.x = __float2half_rn(vx);
                    hp.y = __float2half_rn(vy);
                    *(__half2*)&OutH[orow + n] = hp;
                } else {
                    float2 r = *(const float2*)&resid[orow + n];
                    float2 v = {r.x + vx, r.y + vy};
                    *(float2*)&Cout[orow + n] = v;
                }
            }
        }
    }
}

// ====================== launch ======================
extern "C" void kernel_launch(void* const* d_in, const int* in_sizes, int n_in,
                              void* d_out, int out_size)
{
    (void)in_sizes; (void)n_in; (void)out_size;
    const float* x     = (const float*)d_in[0];
    const float* ln1g  = (const float*)d_in[1];
    const float* ln1b  = (const float*)d_in[2];
    const float* qkvw  = (const float*)d_in[3];
    const float* qkvb  = (const float*)d_in[4];
    const float* rpb   = (const float*)d_in[5];
    const float* projw = (const float*)d_in[6];
    const float* projb = (const float*)d_in[7];
    const float* ln2g  = (const float*)d_in[8];
    const float* ln2b  = (const float*)d_in[9];
    const float* fc1w  = (const float*)d_in[10];
    const float* fc1b  = (const float*)d_in[11];
    const float* fc2w  = (const float*)d_in[12];
    const float* fc2b  = (const float*)d_in[13];
    float* out = (float*)d_out;

    float *X;
    __half *QKV, *A, *H1;
    cudaGetSymbolAddress((void**)&X,   g_X);
    cudaGetSymbolAddress((void**)&QKV, g_QKV);
    cudaGetSymbolAddress((void**)&A,   g_A);
    cudaGetSymbolAddress((void**)&H1,  g_H1);

    __half *Wq, *Wp, *W1, *W2;
    cudaGetSymbolAddress((void**)&Wq, g_Wqkv);
    cudaGetSymbolAddress((void**)&Wp, g_Wprj);
    cudaGetSymbolAddress((void**)&W1, g_Wfc1);
    cudaGetSymbolAddress((void**)&W2, g_Wfc2);

    cudaFuncSetAttribute(gemm_fp16_kernel<0>, cudaFuncAttributeMaxDynamicSharedMemorySize, GSMEM);
    cudaFuncSetAttribute(gemm_fp16_kernel<1>, cudaFuncAttributeMaxDynamicSharedMemorySize, GSMEM);
    cudaFuncSetAttribute(gemm_fp16_kernel<2>, cudaFuncAttributeMaxDynamicSharedMemorySize, GSMEM);
    cudaFuncSetAttribute(gemm_fp16_kernel<3>, cudaFuncAttributeMaxDynamicSharedMemorySize, GSMEM);

    for (int layer = 0; layer < 2; layer++) {
        size_t oq = (size_t)layer * 192 * 576;
        size_t op = (size_t)layer * 192 * 192;
        size_t o1 = (size_t)layer * 192 * 768;
        size_t o2 = (size_t)layer * 768 * 192;
        wsplit_layer_kernel<<<1728, 256>>>(
            qkvw + oq, projw + op, fc1w + o1, fc2w + o2,
            Wq + oq, Wp + op, W1 + o1, W2 + o2);
    }

    const int MB = TTOT / 128;  // 1568
    for (int layer = 0; layer < 2; layer++) {
        int shifted = layer & 1;
        size_t oq = (size_t)layer * 192 * 576;
        size_t op = (size_t)layer * 192 * 192;
        size_t o1 = (size_t)layer * 192 * 768;
        size_t o2 = (size_t)layer * 768 * 192;
        const float* pre = (layer == 0) ? x : X;
        float* fc2_out   = (layer == 0) ? X : out;

        // LN1 + window(+shift) gather -> A (fp16)
        lnsplit_kernel<<<TTOT / 8, 256>>>(pre, A,
            ln1g + layer * CC, ln1b + layer * CC, 1, shifted);
        // QKV = A @ Wq + b  -> fp16 store
        gemm_fp16_kernel<0><<<dim3(9, MB), 256, GSMEM>>>(
            A, Wq + oq, qkvb + layer * 576, nullptr, nullptr, QKV, 576, 192, 0);
        // attention -> A (fp16, window order)
        attn_kernel<<<NWINS * NHEADS, 128>>>(QKV, A, rpb + layer * 169 * NHEADS, shifted);
        // proj + window-reverse(+unshift) + residual -> X (fp32)
        gemm_fp16_kernel<1><<<dim3(3, MB), 256, GSMEM>>>(
            A, Wp + op, projb + layer * CC, X, pre, nullptr, 192, 192, shifted);
        // LN2 -> A (fp16, token order)
        lnsplit_kernel<<<TTOT / 8, 256>>>(X, A,
            ln2g + layer * CC, ln2b + layer * CC, 0, 0);
        // fc1 + GELU -> H1 (fp16)
        gemm_fp16_kernel<2><<<dim3(12, MB), 256, GSMEM>>>(
            A, W1 + o1, fc1b + layer * HIDDIM, nullptr, nullptr, H1, 768, 192, 0);
        // fc2 + residual -> X / d_out (fp32)
        gemm_fp16_kernel<3><<<dim3(3, MB), 256, GSMEM>>>(
            H1, W2 + o2, fc2b + layer * CC, fc2_out, X, nullptr, 192, 768, 0);
    }
}